// round 11
// baseline (speedup 1.0000x reference)
#include <cuda_runtime.h>
#include <cuda_fp16.h>
#include <cstdint>

#define S_LEN 2048
#define DIM   4096
#define HD    128
#define KVD   1024
#define NQKV  6144

__device__ __half g_wqkv[NQKV*DIM];   // rows 0..4095 wq, 4096..5119 wk, 5120..6143 wv
__device__ __half g_wo[DIM*DIM];
__device__ __half g_x [S_LEN*DIM];
__device__ __half g_q [S_LEN*DIM];
__device__ __half g_kb[S_LEN*KVD];
__device__ __half g_vb[S_LEN*KVD];
__device__ __half g_at[S_LEN*DIM];
__device__ unsigned g_gmax[4*64];

__device__ __forceinline__ uint32_t cvta_s(const void* p){
    return (uint32_t)__cvta_generic_to_shared(p);
}
__device__ __forceinline__ void cp16(uint32_t s, const void* g){
    asm volatile("cp.async.cg.shared.global [%0], [%1], 16;\n" :: "r"(s), "l"(g));
}
__device__ __forceinline__ void cp_commit(){ asm volatile("cp.async.commit_group;\n"); }
__device__ __forceinline__ void cp_wait1(){ asm volatile("cp.async.wait_group 1;\n"); }
__device__ __forceinline__ void cp_wait0(){ asm volatile("cp.async.wait_group 0;\n"); }
__device__ __forceinline__ void ldm4(uint32_t& a,uint32_t& b,uint32_t& c,uint32_t& d, uint32_t addr){
    asm volatile("ldmatrix.sync.aligned.m8n8.x4.shared.b16 {%0,%1,%2,%3},[%4];\n"
                 : "=r"(a),"=r"(b),"=r"(c),"=r"(d) : "r"(addr));
}
__device__ __forceinline__ void ldm4t(uint32_t& a,uint32_t& b,uint32_t& c,uint32_t& d, uint32_t addr){
    asm volatile("ldmatrix.sync.aligned.m8n8.x4.trans.shared.b16 {%0,%1,%2,%3},[%4];\n"
                 : "=r"(a),"=r"(b),"=r"(c),"=r"(d) : "r"(addr));
}
__device__ __forceinline__ void mma16816(float* c, uint32_t a0,uint32_t a1,uint32_t a2,uint32_t a3,
                                         uint32_t b0,uint32_t b1){
    asm volatile("mma.sync.aligned.m16n8k16.row.col.f32.f16.f16.f32 "
                 "{%0,%1,%2,%3},{%4,%5,%6,%7},{%8,%9},{%0,%1,%2,%3};\n"
                 : "+f"(c[0]),"+f"(c[1]),"+f"(c[2]),"+f"(c[3])
                 : "r"(a0),"r"(a1),"r"(a2),"r"(a3),"r"(b0),"r"(b1));
}

// ---------------- quantization ----------------
__global__ void zero_gmax_k(unsigned* gm){ gm[threadIdx.x] = 0u; }

__global__ __launch_bounds__(256) void group_max_all(const float* __restrict__ wq,
                                                     const float* __restrict__ wk,
                                                     const float* __restrict__ wv,
                                                     const float* __restrict__ wo,
                                                     unsigned* __restrict__ gm){
    const int w = blockIdx.z;
    const float* W = (w==0) ? wq : (w==1) ? wk : (w==2) ? wv : wo;
    const int rows = (w==0 || w==3) ? DIM : KVD;
    if ((int)blockIdx.y * 8 >= rows) return;
    const float4* base = (const float4*)W + (size_t)blockIdx.y*8*1024 + threadIdx.x;
    unsigned m[4] = {0,0,0,0};
    #pragma unroll
    for (int r = 0; r < 8; r++){
        #pragma unroll
        for (int i = 0; i < 4; i++){
            float4 v = base[(size_t)r*1024 + i*256];
            unsigned b0 = __float_as_uint(v.x) & 0x7fffffffu;
            unsigned b1 = __float_as_uint(v.y) & 0x7fffffffu;
            unsigned b2 = __float_as_uint(v.z) & 0x7fffffffu;
            unsigned b3 = __float_as_uint(v.w) & 0x7fffffffu;
            m[i] = max(m[i], max(max(b0,b1), max(b2,b3)));
        }
    }
    __shared__ unsigned red[64];
    if (threadIdx.x < 64) red[threadIdx.x] = 0u;
    __syncthreads();
    #pragma unroll
    for (int i = 0; i < 4; i++)
        atomicMax(&red[(threadIdx.x + i*256) >> 4], m[i]);
    __syncthreads();
    if (threadIdx.x < 64) atomicMax(&gm[w*64 + threadIdx.x], red[threadIdx.x]);
}

__global__ __launch_bounds__(256) void quant_k(const float* __restrict__ W,
                                               const unsigned* __restrict__ gm,
                                               __half* __restrict__ out, int n4, int cols4){
    for (int idx = blockIdx.x*blockDim.x + threadIdx.x; idx < n4; idx += gridDim.x*blockDim.x){
        float4 v = ((const float4*)W)[idx];
        unsigned Egb = gm[(idx % cols4) >> 4] >> 23;
        float scale = __uint_as_float((Egb - 7u) << 23);
        float in[4] = {v.x, v.y, v.z, v.w};
        float q[4];
        #pragma unroll
        for (int j = 0; j < 4; j++){
            uint32_t b = __float_as_uint(in[j]);
            uint32_t ab = b & 0x7fffffffu;
            int sm = ab ? (int)(0x80u | ((ab >> 16) & 0x7Fu)) : 0;
            int sh = min((int)Egb - (int)(ab >> 23), 31);
            float r = (float)(sm >> sh) * scale;
            q[j] = __uint_as_float(__float_as_uint(r) | (b & 0x80000000u));
        }
        ((__half2*)out)[2*idx]   = __floats2half2_rn(q[0], q[1]);
        ((__half2*)out)[2*idx+1] = __floats2half2_rn(q[2], q[3]);
    }
}

__global__ void f2h_k(const float* __restrict__ x, __half* __restrict__ o, int n4){
    int i = blockIdx.x*blockDim.x + threadIdx.x;
    if (i < n4){
        float4 v = ((const float4*)x)[i];
        ((__half2*)o)[2*i]   = __floats2half2_rn(v.x, v.y);
        ((__half2*)o)[2*i+1] = __floats2half2_rn(v.z, v.w);
    }
}

// C[M,N] = A[M,K]*B[N,K]^T. block 128x128x64, 8 warps (2m x 4n). 3-stage cp.async.
// EPI: 2 = fp32 out (O proj); 3 = fused QKV routing (Q rope*QS, K rope->Kh, V plain->Vh)
#define QSCALE 0.12752551f   // (1/sqrt(128)) * log2(e), folded into Q
template<int EPI>
__global__ __launch_bounds__(256) void gemm_tn(const __half* __restrict__ A, const __half* __restrict__ B,
                                               __half* __restrict__ Ch, __half* __restrict__ Kh,
                                               __half* __restrict__ Vh, float* __restrict__ Cf,
                                               int m_off, int N, int K,
                                               const float* __restrict__ cosp, const float* __restrict__ sinp){
    extern __shared__ __half smem[];
    const int tid = threadIdx.x, lane = tid & 31, warp = tid >> 5;
    const int wm = (warp & 1)*64, wn = (warp >> 1)*32;
    const int bm = m_off + blockIdx.y*128, bn = blockIdx.x*128;
    uint32_t sS = cvta_s(smem);

    auto loadtile = [&](int stage, int k0){
        uint32_t sA = sS + stage*32768, sB = sA + 16384;
        #pragma unroll
        for (int i = 0; i < 4; i++){
            int cid = tid + i*256;
            int row = cid >> 3, ch = cid & 7, sw = ch ^ (row & 7);
            cp16(sA + row*128 + sw*16, A + (size_t)(bm+row)*K + k0 + ch*8);
            cp16(sB + row*128 + sw*16, B + (size_t)(bn+row)*K + k0 + ch*8);
        }
        cp_commit();
    };
    loadtile(0, 0); loadtile(1, 64);

    float acc[4][4][4];
    #pragma unroll
    for (int a=0;a<4;a++) for (int b2=0;b2<4;b2++) for (int c=0;c<4;c++) acc[a][b2][c]=0.f;

    const int nk = K/64;
    int cons = 0;
    for (int kt = 0; kt < nk; kt++){
        if (kt+1 < nk) cp_wait1(); else cp_wait0();
        __syncthreads();
        if (kt+2 < nk){
            int st = cons + 2; if (st >= 3) st -= 3;
            loadtile(st, (kt+2)*64);
        }
        uint32_t baseA = sS + cons*32768, baseB = baseA + 16384;
        #pragma unroll
        for (int ks = 0; ks < 4; ks++){
            uint32_t arg[4][4];
            #pragma unroll
            for (int mi = 0; mi < 4; mi++){
                int row = wm + mi*16 + (lane & 15);
                int col = ks*16 + (lane >> 4)*8;
                ldm4(arg[mi][0],arg[mi][1],arg[mi][2],arg[mi][3],
                     baseA + row*128 + (((col>>3) ^ (row&7))*16));
            }
            uint32_t brg[4][2];
            #pragma unroll
            for (int nj = 0; nj < 2; nj++){
                int g = lane >> 3;
                int row = wn + nj*16 + (g>>1)*8 + (lane & 7);
                int col = ks*16 + (g & 1)*8;
                uint32_t r0,r1,r2,r3;
                ldm4(r0,r1,r2,r3, baseB + row*128 + (((col>>3) ^ (row&7))*16));
                brg[nj*2][0]=r0; brg[nj*2][1]=r1; brg[nj*2+1][0]=r2; brg[nj*2+1][1]=r3;
            }
            #pragma unroll
            for (int mi=0;mi<4;mi++)
                #pragma unroll
                for (int nf=0;nf<4;nf++)
                    mma16816(acc[mi][nf], arg[mi][0],arg[mi][1],arg[mi][2],arg[mi][3],
                             brg[nf][0],brg[nf][1]);
        }
        if (++cons == 3) cons = 0;
    }

    __half* dsth = Ch; int coff = 0; int Nd = DIM; bool rope = true; float vs = 1.f;
    if (EPI == 3){
        if (bn < 4096)      { dsth = Ch; coff = 0;    Nd = DIM; rope = true; vs = QSCALE; }
        else if (bn < 5120) { dsth = Kh; coff = 4096; Nd = KVD; rope = true; }
        else                { dsth = Vh; coff = 5120; Nd = KVD; rope = false; }
    }
    #pragma unroll
    for (int mi=0;mi<4;mi++){
        int r0 = bm + wm + mi*16 + (lane>>2), r1 = r0 + 8;
        #pragma unroll
        for (int nf=0;nf<4;nf++){
            int c0 = bn + wn + nf*8 + 2*(lane&3);
            float v0=acc[mi][nf][0], v1=acc[mi][nf][1], v2=acc[mi][nf][2], v3=acc[mi][nf][3];
            if (EPI == 2){
                Cf[(size_t)r0*N + c0]   = v0; Cf[(size_t)r0*N + c0+1] = v1;
                Cf[(size_t)r1*N + c0]   = v2; Cf[(size_t)r1*N + c0+1] = v3;
            } else {
                int col = c0 - coff;
                if (rope){
                    v0 *= vs; v1 *= vs; v2 *= vs; v3 *= vs;
                    int i0 = (c0 & (HD-1)) >> 1;
                    float cs = cosp[r0*64 + i0], sn = sinp[r0*64 + i0];
                    dsth[(size_t)r0*Nd + col]   = __float2half_rn(v0*cs - v1*sn);
                    dsth[(size_t)r0*Nd + col+1] = __float2half_rn(v0*sn + v1*cs);
                    cs = cosp[r1*64 + i0]; sn = sinp[r1*64 + i0];
                    dsth[(size_t)r1*Nd + col]   = __float2half_rn(v2*cs - v3*sn);
                    dsth[(size_t)r1*Nd + col+1] = __float2half_rn(v2*sn + v3*cs);
                } else {
                    dsth[(size_t)r0*Nd + col]   = __float2half_rn(v0);
                    dsth[(size_t)r0*Nd + col+1] = __float2half_rn(v1);
                    dsth[(size_t)r1*Nd + col]   = __float2half_rn(v2);
                    dsth[(size_t)r1*Nd + col+1] = __float2half_rn(v3);
                }
            }
        }
    }
}

// causal GQA flash attention for qb in [qb_off, qb_off+gridDim.x). Heavy tiles first.
// Q pre-scaled by (1/sqrt(hd))*log2(e): softmax is pure base-2.
__global__ __launch_bounds__(256) void flash_k(const __half* __restrict__ Q, const __half* __restrict__ Kg,
                                               const __half* __restrict__ Vg, __half* __restrict__ O,
                                               int qb_off){
    extern __shared__ __half smemh[];
    __half* Qs = smemh;
    __half* Ks = smemh + 128*128;
    __half* Vs = Ks + 2*64*128;
    const int tid = threadIdx.x, lane = tid & 31, warp = tid >> 5;
    const int qb = qb_off + (gridDim.x - 1 - blockIdx.x);
    const int h = blockIdx.y, kvh = h >> 2;
    uint32_t sQ = cvta_s(Qs), sK = cvta_s(Ks), sV = cvta_s(Vs);

    auto loadKV = [&](int stage, int j){
        const __half* kg = Kg + (size_t)(j*64)*KVD + kvh*HD;
        const __half* vg = Vg + (size_t)(j*64)*KVD + kvh*HD;
        #pragma unroll
        for (int i = 0; i < 4; i++){
            int cid = tid + i*256;
            int row = cid >> 4, ch = cid & 15, sw = ch ^ (row & 7);
            cp16(sK + stage*16384 + row*256 + sw*16, kg + (size_t)row*KVD + ch*8);
            cp16(sV + stage*16384 + row*256 + sw*16, vg + (size_t)row*KVD + ch*8);
        }
        cp_commit();
    };
    const int jmax = 2*qb + 1;
    loadKV(0, 0); loadKV(1, 1);

    {
        const __half* qg = Q + (size_t)(qb*128)*DIM + h*HD;
        #pragma unroll
        for (int i = 0; i < 8; i++){
            int cid = tid + i*256;
            int row = cid >> 4, ch = cid & 15, sw = ch ^ (row & 7);
            *(uint4*)((char*)Qs + row*256 + sw*16) = *(const uint4*)(qg + (size_t)row*DIM + ch*8);
        }
    }

    float o[16][4];
    #pragma unroll
    for (int i=0;i<16;i++){ o[i][0]=0.f;o[i][1]=0.f;o[i][2]=0.f;o[i][3]=0.f; }
    const float NEGINF = __int_as_float(0xff800000);
    float m0 = NEGINF, m1 = NEGINF, l0 = 0.f, l1 = 0.f;
    const int wm = warp*16;
    const int r0g = qb*128 + wm + (lane>>2), r1g = r0g + 8;

    for (int j = 0; j <= jmax; j++){
        if (j < jmax) cp_wait1(); else cp_wait0();
        __syncthreads();
        uint32_t bK = sK + (j&1)*16384, bV = sV + (j&1)*16384;

        float sacc[8][4];
        #pragma unroll
        for (int f=0;f<8;f++){ sacc[f][0]=0.f;sacc[f][1]=0.f;sacc[f][2]=0.f;sacc[f][3]=0.f; }

        #pragma unroll
        for (int ks = 0; ks < 8; ks++){
            int row = wm + (lane & 15);
            int col = ks*16 + (lane >> 4)*8;
            uint32_t a0,a1,a2,a3;
            ldm4(a0,a1,a2,a3, sQ + row*256 + (((col>>3) ^ (row&7))*16));
            #pragma unroll
            for (int nj = 0; nj < 4; nj++){
                int g = lane >> 3;
                int brow = nj*16 + (g>>1)*8 + (lane & 7);
                int bcol = ks*16 + (g & 1)*8;
                uint32_t r0,r1,r2,r3;
                ldm4(r0,r1,r2,r3, bK + brow*256 + (((bcol>>3) ^ (brow&7))*16));
                mma16816(sacc[nj*2],   a0,a1,a2,a3, r0,r1);
                mma16816(sacc[nj*2+1], a0,a1,a2,a3, r2,r3);
            }
        }

        const bool masked = (j >= 2*qb);
        float mx0 = NEGINF, mx1 = NEGINF;
        #pragma unroll
        for (int f = 0; f < 8; f++){
            float v0 = sacc[f][0], v1 = sacc[f][1];
            float v2 = sacc[f][2], v3 = sacc[f][3];
            if (masked){
                int c0 = j*64 + f*8 + 2*(lane & 3);
                if (c0   > r0g) v0 = NEGINF;
                if (c0+1 > r0g) v1 = NEGINF;
                if (c0   > r1g) v2 = NEGINF;
                if (c0+1 > r1g) v3 = NEGINF;
                sacc[f][0]=v0; sacc[f][1]=v1; sacc[f][2]=v2; sacc[f][3]=v3;
            }
            mx0 = fmaxf(mx0, fmaxf(v0, v1));
            mx1 = fmaxf(mx1, fmaxf(v2, v3));
        }
        mx0 = fmaxf(mx0, __shfl_xor_sync(~0u, mx0, 1));
        mx0 = fmaxf(mx0, __shfl_xor_sync(~0u, mx0, 2));
        mx1 = fmaxf(mx1, __shfl_xor_sync(~0u, mx1, 1));
        mx1 = fmaxf(mx1, __shfl_xor_sync(~0u, mx1, 2));
        float nm0 = fmaxf(m0, mx0), nm1 = fmaxf(m1, mx1);
        float al0 = exp2f(m0 - nm0), al1 = exp2f(m1 - nm1);
        m0 = nm0; m1 = nm1;

        float rs0 = 0.f, rs1 = 0.f;
        uint32_t pk[8][2];
        #pragma unroll
        for (int f = 0; f < 8; f++){
            float p0 = exp2f(sacc[f][0]-nm0);
            float p1 = exp2f(sacc[f][1]-nm0);
            float p2 = exp2f(sacc[f][2]-nm1);
            float p3 = exp2f(sacc[f][3]-nm1);
            rs0 += p0 + p1; rs1 += p2 + p3;
            __half2 h01 = __floats2half2_rn(p0, p1);
            __half2 h23 = __floats2half2_rn(p2, p3);
            pk[f][0] = *(uint32_t*)&h01;
            pk[f][1] = *(uint32_t*)&h23;
        }
        rs0 += __shfl_xor_sync(~0u, rs0, 1);
        rs0 += __shfl_xor_sync(~0u, rs0, 2);
        rs1 += __shfl_xor_sync(~0u, rs1, 1);
        rs1 += __shfl_xor_sync(~0u, rs1, 2);
        l0 = l0*al0 + rs0; l1 = l1*al1 + rs1;

        #pragma unroll
        for (int nf=0;nf<16;nf++){
            o[nf][0]*=al0; o[nf][1]*=al0; o[nf][2]*=al1; o[nf][3]*=al1;
        }
        #pragma unroll
        for (int ks = 0; ks < 4; ks++){
            uint32_t a0=pk[2*ks][0], a1=pk[2*ks][1], a2=pk[2*ks+1][0], a3=pk[2*ks+1][1];
            #pragma unroll
            for (int nb = 0; nb < 8; nb++){
                int krow = ks*16 + (lane & 15);
                int ncol = nb*16 + (lane >> 4)*8;
                uint32_t b0,b1,b2,b3;
                ldm4t(b0,b1,b2,b3, bV + krow*256 + (((ncol>>3) ^ (krow&7))*16));
                mma16816(o[2*nb],   a0,a1,a2,a3, b0,b1);
                mma16816(o[2*nb+1], a0,a1,a2,a3, b2,b3);
            }
        }
        __syncthreads();
        if (j+2 <= jmax) loadKV(j&1, j+2);
    }

    float inv0 = 1.f/l0, inv1 = 1.f/l1;
    #pragma unroll
    for (int nf=0;nf<16;nf++){
        int c0 = nf*8 + 2*(lane&3);
        O[(size_t)r0g*DIM + h*HD + c0]   = __float2half_rn(o[nf][0]*inv0);
        O[(size_t)r0g*DIM + h*HD + c0+1] = __float2half_rn(o[nf][1]*inv0);
        O[(size_t)r1g*DIM + h*HD + c0]   = __float2half_rn(o[nf][2]*inv1);
        O[(size_t)r1g*DIM + h*HD + c0+1] = __float2half_rn(o[nf][3]*inv1);
    }
}

extern "C" void kernel_launch(void* const* d_in, const int* in_sizes, int n_in,
                              void* d_out, int out_size) {
    const float* x    = (const float*)d_in[0];
    const float* wq   = (const float*)d_in[1];
    const float* wk   = (const float*)d_in[2];
    const float* wv   = (const float*)d_in[3];
    const float* wo   = (const float*)d_in[4];
    const float* fcos = (const float*)d_in[5];
    const float* fsin = (const float*)d_in[6];

    void *p_wqkv,*p_wo,*p_x,*p_q,*p_kb,*p_vb,*p_at,*p_gm;
    cudaGetSymbolAddress(&p_wqkv, g_wqkv); cudaGetSymbolAddress(&p_wo, g_wo);
    cudaGetSymbolAddress(&p_x,  g_x);  cudaGetSymbolAddress(&p_q,  g_q);
    cudaGetSymbolAddress(&p_kb, g_kb); cudaGetSymbolAddress(&p_vb, g_vb);
    cudaGetSymbolAddress(&p_at, g_at); cudaGetSymbolAddress(&p_gm, g_gmax);
    unsigned* gm = (unsigned*)p_gm;
    __half* hqkv = (__half*)p_wqkv; __half* hwo = (__half*)p_wo;
    __half* hx = (__half*)p_x;  __half* hq = (__half*)p_q;
    __half* hk = (__half*)p_kb; __half* hv = (__half*)p_vb;
    __half* ha = (__half*)p_at;

    cudaFuncSetAttribute(gemm_tn<2>, cudaFuncAttributeMaxDynamicSharedMemorySize, 98304);
    cudaFuncSetAttribute(gemm_tn<3>, cudaFuncAttributeMaxDynamicSharedMemorySize, 98304);
    cudaFuncSetAttribute(flash_k,    cudaFuncAttributeMaxDynamicSharedMemorySize, 98304);

    static cudaStream_t s1 = nullptr, s2 = nullptr, s3 = nullptr;
    static cudaEvent_t e0=nullptr,e1=nullptr,e2=nullptr,e3=nullptr;
    static cudaEvent_t eqlo=nullptr,eolo=nullptr,efh1=nullptr,eomid=nullptr;
    if (!s1){
        cudaStreamCreateWithFlags(&s1, cudaStreamNonBlocking);
        cudaStreamCreateWithFlags(&s2, cudaStreamNonBlocking);
        cudaStreamCreateWithFlags(&s3, cudaStreamNonBlocking);
        cudaEventCreateWithFlags(&e0,  cudaEventDisableTiming);
        cudaEventCreateWithFlags(&e1,  cudaEventDisableTiming);
        cudaEventCreateWithFlags(&e2,  cudaEventDisableTiming);
        cudaEventCreateWithFlags(&e3,  cudaEventDisableTiming);
        cudaEventCreateWithFlags(&eqlo,cudaEventDisableTiming);
        cudaEventCreateWithFlags(&eolo,cudaEventDisableTiming);
        cudaEventCreateWithFlags(&efh1,cudaEventDisableTiming);
        cudaEventCreateWithFlags(&eomid,cudaEventDisableTiming);
    }

    // ---- prologue: gmax on default; f2h overlapped on s2 ----
    zero_gmax_k<<<1,256>>>(gm);
    group_max_all<<<dim3(1,512,4),256>>>(wq, wk, wv, wo, gm);
    cudaEventRecord(e0, 0);

    f2h_k<<<(S_LEN*DIM/4+255)/256,256,0,s2>>>(x, hx, S_LEN*DIM/4);
    cudaStreamWaitEvent(s2, e0, 0);
    quant_k<<<1024,256,0,s2>>>(wv, gm+128, hqkv + (size_t)5120*DIM, KVD*DIM/4, DIM/4);
    cudaEventRecord(e2, s2);

    cudaStreamWaitEvent(s1, e0, 0);
    quant_k<<<1024,256,0,s1>>>(wk, gm+64, hqkv + (size_t)4096*DIM, KVD*DIM/4, DIM/4);
    cudaEventRecord(e1, s1);

    cudaStreamWaitEvent(s3, e0, 0);
    quant_k<<<2048,256,0,s3>>>(wo, gm+192, hwo, DIM*DIM/4, DIM/4);
    cudaEventRecord(e3, s3);

    // default: wq quant -> fused QKV GEMM lo/hi
    quant_k<<<2048,256>>>(wq, gm+0, hqkv, DIM*DIM/4, DIM/4);
    cudaStreamWaitEvent(0, e1, 0);
    cudaStreamWaitEvent(0, e2, 0);
    gemm_tn<3><<<dim3(48,8),256,98304>>>(hx, hqkv, hq, hk, hv, nullptr,
                                         0, NQKV, DIM, fcos, fsin);
    cudaEventRecord(eqlo, 0);
    gemm_tn<3><<<dim3(48,8),256,98304>>>(hx, hqkv, hq, hk, hv, nullptr,
                                         1024, NQKV, DIM, fcos, fsin);

    // s1: flash-lo (qb 0..7) -> O rows 0..1023
    cudaStreamWaitEvent(s1, eqlo, 0);
    flash_k<<<dim3(8,32),256,98304,s1>>>(hq, hk, hv, ha, 0);
    cudaStreamWaitEvent(s1, e3, 0);
    gemm_tn<2><<<dim3(32,8),256,98304,s1>>>(ha, hwo, nullptr, nullptr, nullptr, (float*)d_out,
                                            0, DIM, DIM, nullptr, nullptr);
    cudaEventRecord(eolo, s1);

    // default: flash qb 8..11 -> [efh1] -> flash qb 12..15
    flash_k<<<dim3(4,32),256,98304>>>(hq, hk, hv, ha, 8);
    cudaEventRecord(efh1, 0);
    flash_k<<<dim3(4,32),256,98304>>>(hq, hk, hv, ha, 12);

    // s2: O rows 1024..1535 overlaps flash qb 12..15
    cudaStreamWaitEvent(s2, efh1, 0);
    cudaStreamWaitEvent(s2, e3, 0);
    gemm_tn<2><<<dim3(32,4),256,98304,s2>>>(ha, hwo, nullptr, nullptr, nullptr, (float*)d_out,
                                            1024, DIM, DIM, nullptr, nullptr);
    cudaEventRecord(eomid, s2);

    // default: O rows 1536..2047, then join
    cudaStreamWaitEvent(0, e3, 0);
    gemm_tn<2><<<dim3(32,4),256,98304>>>(ha, hwo, nullptr, nullptr, nullptr, (float*)d_out,
                                         1536, DIM, DIM, nullptr, nullptr);
    cudaStreamWaitEvent(0, eolo, 0);
    cudaStreamWaitEvent(0, eomid, 0);
}

// round 12
// speedup vs baseline: 1.0342x; 1.0342x over previous
#include <cuda_runtime.h>
#include <cuda_fp16.h>
#include <cstdint>

#define S_LEN 2048
#define DIM   4096
#define HD    128
#define KVD   1024
#define NQKV  6144

__device__ __half g_wqkv[NQKV*DIM];   // rows 0..4095 wq, 4096..5119 wk, 5120..6143 wv
__device__ __half g_wo[DIM*DIM];
__device__ __half g_x [S_LEN*DIM];
__device__ __half g_q [S_LEN*DIM];
__device__ __half g_kb[S_LEN*KVD];
__device__ __half g_vb[S_LEN*KVD];
__device__ __half g_at[S_LEN*DIM];
__device__ unsigned g_gmax[4*64];

__device__ __forceinline__ uint32_t cvta_s(const void* p){
    return (uint32_t)__cvta_generic_to_shared(p);
}
__device__ __forceinline__ void cp16(uint32_t s, const void* g){
    asm volatile("cp.async.cg.shared.global [%0], [%1], 16;\n" :: "r"(s), "l"(g));
}
__device__ __forceinline__ void cp_commit(){ asm volatile("cp.async.commit_group;\n"); }
__device__ __forceinline__ void cp_wait1(){ asm volatile("cp.async.wait_group 1;\n"); }
__device__ __forceinline__ void cp_wait0(){ asm volatile("cp.async.wait_group 0;\n"); }
__device__ __forceinline__ void ldm4(uint32_t& a,uint32_t& b,uint32_t& c,uint32_t& d, uint32_t addr){
    asm volatile("ldmatrix.sync.aligned.m8n8.x4.shared.b16 {%0,%1,%2,%3},[%4];\n"
                 : "=r"(a),"=r"(b),"=r"(c),"=r"(d) : "r"(addr));
}
__device__ __forceinline__ void ldm4t(uint32_t& a,uint32_t& b,uint32_t& c,uint32_t& d, uint32_t addr){
    asm volatile("ldmatrix.sync.aligned.m8n8.x4.trans.shared.b16 {%0,%1,%2,%3},[%4];\n"
                 : "=r"(a),"=r"(b),"=r"(c),"=r"(d) : "r"(addr));
}
__device__ __forceinline__ void mma16816(float* c, uint32_t a0,uint32_t a1,uint32_t a2,uint32_t a3,
                                         uint32_t b0,uint32_t b1){
    asm volatile("mma.sync.aligned.m16n8k16.row.col.f32.f16.f16.f32 "
                 "{%0,%1,%2,%3},{%4,%5,%6,%7},{%8,%9},{%0,%1,%2,%3};\n"
                 : "+f"(c[0]),"+f"(c[1]),"+f"(c[2]),"+f"(c[3])
                 : "r"(a0),"r"(a1),"r"(a2),"r"(a3),"r"(b0),"r"(b1));
}

// ---------------- quantization ----------------
__global__ void zero_gmax_k(unsigned* gm){ gm[threadIdx.x] = 0u; }

// Per-weight group max: block = contiguous 8-row x 4096-col band, coalesced float4,
// 64 smem group maxes, one atomicMax per group.
__global__ __launch_bounds__(256) void group_max_w(const float* __restrict__ W,
                                                   unsigned* __restrict__ gm){
    const float4* base = (const float4*)W + (size_t)blockIdx.y*8*1024 + threadIdx.x;
    unsigned m[4] = {0,0,0,0};
    #pragma unroll
    for (int r = 0; r < 8; r++){
        #pragma unroll
        for (int i = 0; i < 4; i++){
            float4 v = base[(size_t)r*1024 + i*256];
            unsigned b0 = __float_as_uint(v.x) & 0x7fffffffu;
            unsigned b1 = __float_as_uint(v.y) & 0x7fffffffu;
            unsigned b2 = __float_as_uint(v.z) & 0x7fffffffu;
            unsigned b3 = __float_as_uint(v.w) & 0x7fffffffu;
            m[i] = max(m[i], max(max(b0,b1), max(b2,b3)));
        }
    }
    __shared__ unsigned red[64];
    if (threadIdx.x < 64) red[threadIdx.x] = 0u;
    __syncthreads();
    #pragma unroll
    for (int i = 0; i < 4; i++)
        atomicMax(&red[(threadIdx.x + i*256) >> 4], m[i]);
    __syncthreads();
    if (threadIdx.x < 64) atomicMax(&gm[threadIdx.x], red[threadIdx.x]);
}

__global__ __launch_bounds__(256) void quant_k(const float* __restrict__ W,
                                               const unsigned* __restrict__ gm,
                                               __half* __restrict__ out, int n4, int cols4){
    for (int idx = blockIdx.x*blockDim.x + threadIdx.x; idx < n4; idx += gridDim.x*blockDim.x){
        float4 v = ((const float4*)W)[idx];
        unsigned Egb = gm[(idx % cols4) >> 4] >> 23;
        float scale = __uint_as_float((Egb - 7u) << 23);
        float in[4] = {v.x, v.y, v.z, v.w};
        float q[4];
        #pragma unroll
        for (int j = 0; j < 4; j++){
            uint32_t b = __float_as_uint(in[j]);
            uint32_t ab = b & 0x7fffffffu;
            int sm = ab ? (int)(0x80u | ((ab >> 16) & 0x7Fu)) : 0;
            int sh = min((int)Egb - (int)(ab >> 23), 31);
            float r = (float)(sm >> sh) * scale;
            q[j] = __uint_as_float(__float_as_uint(r) | (b & 0x80000000u));
        }
        ((__half2*)out)[2*idx]   = __floats2half2_rn(q[0], q[1]);
        ((__half2*)out)[2*idx+1] = __floats2half2_rn(q[2], q[3]);
    }
}

__global__ void f2h_k(const float* __restrict__ x, __half* __restrict__ o, int n4){
    int i = blockIdx.x*blockDim.x + threadIdx.x;
    if (i < n4){
        float4 v = ((const float4*)x)[i];
        ((__half2*)o)[2*i]   = __floats2half2_rn(v.x, v.y);
        ((__half2*)o)[2*i+1] = __floats2half2_rn(v.z, v.w);
    }
}

// C[M,N] = A[M,K]*B[N,K]^T. block 128x128x64, 8 warps (2m x 4n). 3-stage cp.async.
// EPI: 2 = fp32 out (O proj); 3 = fused QKV routing (Q rope*QS, K rope->Kh, V plain->Vh)
#define QSCALE 0.12752551f   // (1/sqrt(128)) * log2(e), folded into Q
template<int EPI>
__global__ __launch_bounds__(256) void gemm_tn(const __half* __restrict__ A, const __half* __restrict__ B,
                                               __half* __restrict__ Ch, __half* __restrict__ Kh,
                                               __half* __restrict__ Vh, float* __restrict__ Cf,
                                               int m_off, int N, int K,
                                               const float* __restrict__ cosp, const float* __restrict__ sinp){
    extern __shared__ __half smem[];
    const int tid = threadIdx.x, lane = tid & 31, warp = tid >> 5;
    const int wm = (warp & 1)*64, wn = (warp >> 1)*32;
    const int bm = m_off + blockIdx.y*128, bn = blockIdx.x*128;
    uint32_t sS = cvta_s(smem);

    auto loadtile = [&](int stage, int k0){
        uint32_t sA = sS + stage*32768, sB = sA + 16384;
        #pragma unroll
        for (int i = 0; i < 4; i++){
            int cid = tid + i*256;
            int row = cid >> 3, ch = cid & 7, sw = ch ^ (row & 7);
            cp16(sA + row*128 + sw*16, A + (size_t)(bm+row)*K + k0 + ch*8);
            cp16(sB + row*128 + sw*16, B + (size_t)(bn+row)*K + k0 + ch*8);
        }
        cp_commit();
    };
    loadtile(0, 0); loadtile(1, 64);

    float acc[4][4][4];
    #pragma unroll
    for (int a=0;a<4;a++) for (int b2=0;b2<4;b2++) for (int c=0;c<4;c++) acc[a][b2][c]=0.f;

    const int nk = K/64;
    int cons = 0;
    for (int kt = 0; kt < nk; kt++){
        if (kt+1 < nk) cp_wait1(); else cp_wait0();
        __syncthreads();
        if (kt+2 < nk){
            int st = cons + 2; if (st >= 3) st -= 3;
            loadtile(st, (kt+2)*64);
        }
        uint32_t baseA = sS + cons*32768, baseB = baseA + 16384;
        #pragma unroll
        for (int ks = 0; ks < 4; ks++){
            uint32_t arg[4][4];
            #pragma unroll
            for (int mi = 0; mi < 4; mi++){
                int row = wm + mi*16 + (lane & 15);
                int col = ks*16 + (lane >> 4)*8;
                ldm4(arg[mi][0],arg[mi][1],arg[mi][2],arg[mi][3],
                     baseA + row*128 + (((col>>3) ^ (row&7))*16));
            }
            uint32_t brg[4][2];
            #pragma unroll
            for (int nj = 0; nj < 2; nj++){
                int g = lane >> 3;
                int row = wn + nj*16 + (g>>1)*8 + (lane & 7);
                int col = ks*16 + (g & 1)*8;
                uint32_t r0,r1,r2,r3;
                ldm4(r0,r1,r2,r3, baseB + row*128 + (((col>>3) ^ (row&7))*16));
                brg[nj*2][0]=r0; brg[nj*2][1]=r1; brg[nj*2+1][0]=r2; brg[nj*2+1][1]=r3;
            }
            #pragma unroll
            for (int mi=0;mi<4;mi++)
                #pragma unroll
                for (int nf=0;nf<4;nf++)
                    mma16816(acc[mi][nf], arg[mi][0],arg[mi][1],arg[mi][2],arg[mi][3],
                             brg[nf][0],brg[nf][1]);
        }
        if (++cons == 3) cons = 0;
    }

    __half* dsth = Ch; int coff = 0; int Nd = DIM; bool rope = true; float vs = 1.f;
    if (EPI == 3){
        if (bn < 4096)      { dsth = Ch; coff = 0;    Nd = DIM; rope = true; vs = QSCALE; }
        else if (bn < 5120) { dsth = Kh; coff = 4096; Nd = KVD; rope = true; }
        else                { dsth = Vh; coff = 5120; Nd = KVD; rope = false; }
    }
    #pragma unroll
    for (int mi=0;mi<4;mi++){
        int r0 = bm + wm + mi*16 + (lane>>2), r1 = r0 + 8;
        #pragma unroll
        for (int nf=0;nf<4;nf++){
            int c0 = bn + wn + nf*8 + 2*(lane&3);
            float v0=acc[mi][nf][0], v1=acc[mi][nf][1], v2=acc[mi][nf][2], v3=acc[mi][nf][3];
            if (EPI == 2){
                Cf[(size_t)r0*N + c0]   = v0; Cf[(size_t)r0*N + c0+1] = v1;
                Cf[(size_t)r1*N + c0]   = v2; Cf[(size_t)r1*N + c0+1] = v3;
            } else {
                int col = c0 - coff;
                if (rope){
                    v0 *= vs; v1 *= vs; v2 *= vs; v3 *= vs;
                    int i0 = (c0 & (HD-1)) >> 1;
                    float cs = cosp[r0*64 + i0], sn = sinp[r0*64 + i0];
                    dsth[(size_t)r0*Nd + col]   = __float2half_rn(v0*cs - v1*sn);
                    dsth[(size_t)r0*Nd + col+1] = __float2half_rn(v0*sn + v1*cs);
                    cs = cosp[r1*64 + i0]; sn = sinp[r1*64 + i0];
                    dsth[(size_t)r1*Nd + col]   = __float2half_rn(v2*cs - v3*sn);
                    dsth[(size_t)r1*Nd + col+1] = __float2half_rn(v2*sn + v3*cs);
                } else {
                    dsth[(size_t)r0*Nd + col]   = __float2half_rn(v0);
                    dsth[(size_t)r0*Nd + col+1] = __float2half_rn(v1);
                    dsth[(size_t)r1*Nd + col]   = __float2half_rn(v2);
                    dsth[(size_t)r1*Nd + col+1] = __float2half_rn(v3);
                }
            }
        }
    }
}

// causal GQA flash attention for qb in [qb_off, qb_off+gridDim.x). Heavy tiles first.
// Q pre-scaled by (1/sqrt(hd))*log2(e): softmax is pure base-2.
__global__ __launch_bounds__(256) void flash_k(const __half* __restrict__ Q, const __half* __restrict__ Kg,
                                               const __half* __restrict__ Vg, __half* __restrict__ O,
                                               int qb_off){
    extern __shared__ __half smemh[];
    __half* Qs = smemh;
    __half* Ks = smemh + 128*128;
    __half* Vs = Ks + 2*64*128;
    const int tid = threadIdx.x, lane = tid & 31, warp = tid >> 5;
    const int qb = qb_off + (gridDim.x - 1 - blockIdx.x);
    const int h = blockIdx.y, kvh = h >> 2;
    uint32_t sQ = cvta_s(Qs), sK = cvta_s(Ks), sV = cvta_s(Vs);

    auto loadKV = [&](int stage, int j){
        const __half* kg = Kg + (size_t)(j*64)*KVD + kvh*HD;
        const __half* vg = Vg + (size_t)(j*64)*KVD + kvh*HD;
        #pragma unroll
        for (int i = 0; i < 4; i++){
            int cid = tid + i*256;
            int row = cid >> 4, ch = cid & 15, sw = ch ^ (row & 7);
            cp16(sK + stage*16384 + row*256 + sw*16, kg + (size_t)row*KVD + ch*8);
            cp16(sV + stage*16384 + row*256 + sw*16, vg + (size_t)row*KVD + ch*8);
        }
        cp_commit();
    };
    const int jmax = 2*qb + 1;
    loadKV(0, 0); loadKV(1, 1);

    {
        const __half* qg = Q + (size_t)(qb*128)*DIM + h*HD;
        #pragma unroll
        for (int i = 0; i < 8; i++){
            int cid = tid + i*256;
            int row = cid >> 4, ch = cid & 15, sw = ch ^ (row & 7);
            *(uint4*)((char*)Qs + row*256 + sw*16) = *(const uint4*)(qg + (size_t)row*DIM + ch*8);
        }
    }

    float o[16][4];
    #pragma unroll
    for (int i=0;i<16;i++){ o[i][0]=0.f;o[i][1]=0.f;o[i][2]=0.f;o[i][3]=0.f; }
    const float NEGINF = __int_as_float(0xff800000);
    float m0 = NEGINF, m1 = NEGINF, l0 = 0.f, l1 = 0.f;
    const int wm = warp*16;
    const int r0g = qb*128 + wm + (lane>>2), r1g = r0g + 8;

    for (int j = 0; j <= jmax; j++){
        if (j < jmax) cp_wait1(); else cp_wait0();
        __syncthreads();
        uint32_t bK = sK + (j&1)*16384, bV = sV + (j&1)*16384;

        float sacc[8][4];
        #pragma unroll
        for (int f=0;f<8;f++){ sacc[f][0]=0.f;sacc[f][1]=0.f;sacc[f][2]=0.f;sacc[f][3]=0.f; }

        #pragma unroll
        for (int ks = 0; ks < 8; ks++){
            int row = wm + (lane & 15);
            int col = ks*16 + (lane >> 4)*8;
            uint32_t a0,a1,a2,a3;
            ldm4(a0,a1,a2,a3, sQ + row*256 + (((col>>3) ^ (row&7))*16));
            #pragma unroll
            for (int nj = 0; nj < 4; nj++){
                int g = lane >> 3;
                int brow = nj*16 + (g>>1)*8 + (lane & 7);
                int bcol = ks*16 + (g & 1)*8;
                uint32_t r0,r1,r2,r3;
                ldm4(r0,r1,r2,r3, bK + brow*256 + (((bcol>>3) ^ (brow&7))*16));
                mma16816(sacc[nj*2],   a0,a1,a2,a3, r0,r1);
                mma16816(sacc[nj*2+1], a0,a1,a2,a3, r2,r3);
            }
        }

        const bool masked = (j >= 2*qb);
        float mx0 = NEGINF, mx1 = NEGINF;
        #pragma unroll
        for (int f = 0; f < 8; f++){
            float v0 = sacc[f][0], v1 = sacc[f][1];
            float v2 = sacc[f][2], v3 = sacc[f][3];
            if (masked){
                int c0 = j*64 + f*8 + 2*(lane & 3);
                if (c0   > r0g) v0 = NEGINF;
                if (c0+1 > r0g) v1 = NEGINF;
                if (c0   > r1g) v2 = NEGINF;
                if (c0+1 > r1g) v3 = NEGINF;
                sacc[f][0]=v0; sacc[f][1]=v1; sacc[f][2]=v2; sacc[f][3]=v3;
            }
            mx0 = fmaxf(mx0, fmaxf(v0, v1));
            mx1 = fmaxf(mx1, fmaxf(v2, v3));
        }
        mx0 = fmaxf(mx0, __shfl_xor_sync(~0u, mx0, 1));
        mx0 = fmaxf(mx0, __shfl_xor_sync(~0u, mx0, 2));
        mx1 = fmaxf(mx1, __shfl_xor_sync(~0u, mx1, 1));
        mx1 = fmaxf(mx1, __shfl_xor_sync(~0u, mx1, 2));
        float nm0 = fmaxf(m0, mx0), nm1 = fmaxf(m1, mx1);
        float al0 = exp2f(m0 - nm0), al1 = exp2f(m1 - nm1);
        m0 = nm0; m1 = nm1;

        float rs0 = 0.f, rs1 = 0.f;
        uint32_t pk[8][2];
        #pragma unroll
        for (int f = 0; f < 8; f++){
            float p0 = exp2f(sacc[f][0]-nm0);
            float p1 = exp2f(sacc[f][1]-nm0);
            float p2 = exp2f(sacc[f][2]-nm1);
            float p3 = exp2f(sacc[f][3]-nm1);
            rs0 += p0 + p1; rs1 += p2 + p3;
            __half2 h01 = __floats2half2_rn(p0, p1);
            __half2 h23 = __floats2half2_rn(p2, p3);
            pk[f][0] = *(uint32_t*)&h01;
            pk[f][1] = *(uint32_t*)&h23;
        }
        rs0 += __shfl_xor_sync(~0u, rs0, 1);
        rs0 += __shfl_xor_sync(~0u, rs0, 2);
        rs1 += __shfl_xor_sync(~0u, rs1, 1);
        rs1 += __shfl_xor_sync(~0u, rs1, 2);
        l0 = l0*al0 + rs0; l1 = l1*al1 + rs1;

        #pragma unroll
        for (int nf=0;nf<16;nf++){
            o[nf][0]*=al0; o[nf][1]*=al0; o[nf][2]*=al1; o[nf][3]*=al1;
        }
        #pragma unroll
        for (int ks = 0; ks < 4; ks++){
            uint32_t a0=pk[2*ks][0], a1=pk[2*ks][1], a2=pk[2*ks+1][0], a3=pk[2*ks+1][1];
            #pragma unroll
            for (int nb = 0; nb < 8; nb++){
                int krow = ks*16 + (lane & 15);
                int ncol = nb*16 + (lane >> 4)*8;
                uint32_t b0,b1,b2,b3;
                ldm4t(b0,b1,b2,b3, bV + krow*256 + (((ncol>>3) ^ (krow&7))*16));
                mma16816(o[2*nb],   a0,a1,a2,a3, b0,b1);
                mma16816(o[2*nb+1], a0,a1,a2,a3, b2,b3);
            }
        }
        __syncthreads();
        if (j+2 <= jmax) loadKV(j&1, j+2);
    }

    float inv0 = 1.f/l0, inv1 = 1.f/l1;
    #pragma unroll
    for (int nf=0;nf<16;nf++){
        int c0 = nf*8 + 2*(lane&3);
        O[(size_t)r0g*DIM + h*HD + c0]   = __float2half_rn(o[nf][0]*inv0);
        O[(size_t)r0g*DIM + h*HD + c0+1] = __float2half_rn(o[nf][1]*inv0);
        O[(size_t)r1g*DIM + h*HD + c0]   = __float2half_rn(o[nf][2]*inv1);
        O[(size_t)r1g*DIM + h*HD + c0+1] = __float2half_rn(o[nf][3]*inv1);
    }
}

extern "C" void kernel_launch(void* const* d_in, const int* in_sizes, int n_in,
                              void* d_out, int out_size) {
    const float* x    = (const float*)d_in[0];
    const float* wq   = (const float*)d_in[1];
    const float* wk   = (const float*)d_in[2];
    const float* wv   = (const float*)d_in[3];
    const float* wo   = (const float*)d_in[4];
    const float* fcos = (const float*)d_in[5];
    const float* fsin = (const float*)d_in[6];

    void *p_wqkv,*p_wo,*p_x,*p_q,*p_kb,*p_vb,*p_at,*p_gm;
    cudaGetSymbolAddress(&p_wqkv, g_wqkv); cudaGetSymbolAddress(&p_wo, g_wo);
    cudaGetSymbolAddress(&p_x,  g_x);  cudaGetSymbolAddress(&p_q,  g_q);
    cudaGetSymbolAddress(&p_kb, g_kb); cudaGetSymbolAddress(&p_vb, g_vb);
    cudaGetSymbolAddress(&p_at, g_at); cudaGetSymbolAddress(&p_gm, g_gmax);
    unsigned* gm = (unsigned*)p_gm;
    __half* hqkv = (__half*)p_wqkv; __half* hwo = (__half*)p_wo;
    __half* hx = (__half*)p_x;  __half* hq = (__half*)p_q;
    __half* hk = (__half*)p_kb; __half* hv = (__half*)p_vb;
    __half* ha = (__half*)p_at;

    cudaFuncSetAttribute(gemm_tn<2>, cudaFuncAttributeMaxDynamicSharedMemorySize, 98304);
    cudaFuncSetAttribute(gemm_tn<3>, cudaFuncAttributeMaxDynamicSharedMemorySize, 98304);
    cudaFuncSetAttribute(flash_k,    cudaFuncAttributeMaxDynamicSharedMemorySize, 98304);

    static cudaStream_t s1 = nullptr, s2 = nullptr, s3 = nullptr;
    static cudaEvent_t e00=nullptr,e1=nullptr,e2=nullptr,e3=nullptr,eqlo=nullptr,eolo=nullptr;
    if (!s1){
        cudaStreamCreateWithFlags(&s1, cudaStreamNonBlocking);
        cudaStreamCreateWithFlags(&s2, cudaStreamNonBlocking);
        cudaStreamCreateWithFlags(&s3, cudaStreamNonBlocking);
        cudaEventCreateWithFlags(&e00, cudaEventDisableTiming);
        cudaEventCreateWithFlags(&e1,  cudaEventDisableTiming);
        cudaEventCreateWithFlags(&e2,  cudaEventDisableTiming);
        cudaEventCreateWithFlags(&e3,  cudaEventDisableTiming);
        cudaEventCreateWithFlags(&eqlo,cudaEventDisableTiming);
        cudaEventCreateWithFlags(&eolo,cudaEventDisableTiming);
    }

    // ---- prologue: zero, then per-weight gmax+quant on each branch stream ----
    zero_gmax_k<<<1,256>>>(gm);
    cudaEventRecord(e00, 0);

    cudaStreamWaitEvent(s1, e00, 0);
    group_max_w<<<dim3(1,KVD/8),256,0,s1>>>(wk, gm+64);
    quant_k<<<1024,256,0,s1>>>(wk, gm+64, hqkv + (size_t)4096*DIM, KVD*DIM/4, DIM/4);
    cudaEventRecord(e1, s1);

    f2h_k<<<(S_LEN*DIM/4+255)/256,256,0,s2>>>(x, hx, S_LEN*DIM/4);
    cudaStreamWaitEvent(s2, e00, 0);
    group_max_w<<<dim3(1,KVD/8),256,0,s2>>>(wv, gm+128);
    quant_k<<<1024,256,0,s2>>>(wv, gm+128, hqkv + (size_t)5120*DIM, KVD*DIM/4, DIM/4);
    cudaEventRecord(e2, s2);

    cudaStreamWaitEvent(s3, e00, 0);
    group_max_w<<<dim3(1,DIM/8),256,0,s3>>>(wo, gm+192);
    quant_k<<<2048,256,0,s3>>>(wo, gm+192, hwo, DIM*DIM/4, DIM/4);
    cudaEventRecord(e3, s3);

    // default: gmax(wq) -> quant(wq) -> fused QKV GEMM lo/hi
    group_max_w<<<dim3(1,DIM/8),256>>>(wq, gm+0);
    quant_k<<<2048,256>>>(wq, gm+0, hqkv, DIM*DIM/4, DIM/4);
    cudaStreamWaitEvent(0, e1, 0);
    cudaStreamWaitEvent(0, e2, 0);
    gemm_tn<3><<<dim3(48,8),256,98304>>>(hx, hqkv, hq, hk, hv, nullptr,
                                         0, NQKV, DIM, fcos, fsin);
    cudaEventRecord(eqlo, 0);
    gemm_tn<3><<<dim3(48,8),256,98304>>>(hx, hqkv, hq, hk, hv, nullptr,
                                         1024, NQKV, DIM, fcos, fsin);

    // s1: flash-lo (qb 0..7) -> O rows 0..1023
    cudaStreamWaitEvent(s1, eqlo, 0);
    flash_k<<<dim3(8,32),256,98304,s1>>>(hq, hk, hv, ha, 0);
    cudaStreamWaitEvent(s1, e3, 0);
    gemm_tn<2><<<dim3(32,8),256,98304,s1>>>(ha, hwo, nullptr, nullptr, nullptr, (float*)d_out,
                                            0, DIM, DIM, nullptr, nullptr);
    cudaEventRecord(eolo, s1);

    // default: flash-hi -> O-hi
    flash_k<<<dim3(8,32),256,98304>>>(hq, hk, hv, ha, 8);
    cudaStreamWaitEvent(0, e3, 0);
    gemm_tn<2><<<dim3(32,8),256,98304>>>(ha, hwo, nullptr, nullptr, nullptr, (float*)d_out,
                                         1024, DIM, DIM, nullptr, nullptr);
    cudaStreamWaitEvent(0, eolo, 0);
}

// round 13
// speedup vs baseline: 1.0397x; 1.0054x over previous
#include <cuda_runtime.h>
#include <cuda_fp16.h>
#include <cstdint>

#define S_LEN 2048
#define DIM   4096
#define HD    128
#define KVD   1024
#define NQKV  6144

__device__ __half g_wqkv[NQKV*DIM];   // rows 0..4095 wq, 4096..5119 wk, 5120..6143 wv
__device__ __half g_wo[DIM*DIM];
__device__ __half g_x [S_LEN*DIM];
__device__ __half g_q [S_LEN*DIM];
__device__ __half g_kb[S_LEN*KVD];
__device__ __half g_vb[S_LEN*KVD];
__device__ __half g_at[S_LEN*DIM];
__device__ unsigned g_gmax[4*64];

__device__ __forceinline__ uint32_t cvta_s(const void* p){
    return (uint32_t)__cvta_generic_to_shared(p);
}
__device__ __forceinline__ void cp16(uint32_t s, const void* g){
    asm volatile("cp.async.cg.shared.global [%0], [%1], 16;\n" :: "r"(s), "l"(g));
}
__device__ __forceinline__ void cp_commit(){ asm volatile("cp.async.commit_group;\n"); }
__device__ __forceinline__ void cp_wait1(){ asm volatile("cp.async.wait_group 1;\n"); }
__device__ __forceinline__ void cp_wait0(){ asm volatile("cp.async.wait_group 0;\n"); }
__device__ __forceinline__ void ldm4(uint32_t& a,uint32_t& b,uint32_t& c,uint32_t& d, uint32_t addr){
    asm volatile("ldmatrix.sync.aligned.m8n8.x4.shared.b16 {%0,%1,%2,%3},[%4];\n"
                 : "=r"(a),"=r"(b),"=r"(c),"=r"(d) : "r"(addr));
}
__device__ __forceinline__ void ldm4t(uint32_t& a,uint32_t& b,uint32_t& c,uint32_t& d, uint32_t addr){
    asm volatile("ldmatrix.sync.aligned.m8n8.x4.trans.shared.b16 {%0,%1,%2,%3},[%4];\n"
                 : "=r"(a),"=r"(b),"=r"(c),"=r"(d) : "r"(addr));
}
__device__ __forceinline__ void mma16816(float* c, uint32_t a0,uint32_t a1,uint32_t a2,uint32_t a3,
                                         uint32_t b0,uint32_t b1){
    asm volatile("mma.sync.aligned.m16n8k16.row.col.f32.f16.f16.f32 "
                 "{%0,%1,%2,%3},{%4,%5,%6,%7},{%8,%9},{%0,%1,%2,%3};\n"
                 : "+f"(c[0]),"+f"(c[1]),"+f"(c[2]),"+f"(c[3])
                 : "r"(a0),"r"(a1),"r"(a2),"r"(a3),"r"(b0),"r"(b1));
}

// ---------------- quantization ----------------
__global__ void zero_gmax_k(unsigned* gm){ gm[threadIdx.x] = 0u; }

__global__ __launch_bounds__(256) void group_max_w(const float* __restrict__ W,
                                                   unsigned* __restrict__ gm){
    const float4* base = (const float4*)W + (size_t)blockIdx.y*8*1024 + threadIdx.x;
    unsigned m[4] = {0,0,0,0};
    #pragma unroll
    for (int r = 0; r < 8; r++){
        #pragma unroll
        for (int i = 0; i < 4; i++){
            float4 v = base[(size_t)r*1024 + i*256];
            unsigned b0 = __float_as_uint(v.x) & 0x7fffffffu;
            unsigned b1 = __float_as_uint(v.y) & 0x7fffffffu;
            unsigned b2 = __float_as_uint(v.z) & 0x7fffffffu;
            unsigned b3 = __float_as_uint(v.w) & 0x7fffffffu;
            m[i] = max(m[i], max(max(b0,b1), max(b2,b3)));
        }
    }
    __shared__ unsigned red[64];
    if (threadIdx.x < 64) red[threadIdx.x] = 0u;
    __syncthreads();
    #pragma unroll
    for (int i = 0; i < 4; i++)
        atomicMax(&red[(threadIdx.x + i*256) >> 4], m[i]);
    __syncthreads();
    if (threadIdx.x < 64) atomicMax(&gm[threadIdx.x], red[threadIdx.x]);
}

__global__ __launch_bounds__(256) void quant_k(const float* __restrict__ W,
                                               const unsigned* __restrict__ gm,
                                               __half* __restrict__ out, int n4, int cols4){
    for (int idx = blockIdx.x*blockDim.x + threadIdx.x; idx < n4; idx += gridDim.x*blockDim.x){
        float4 v = ((const float4*)W)[idx];
        unsigned Egb = gm[(idx % cols4) >> 4] >> 23;
        float scale = __uint_as_float((Egb - 7u) << 23);
        float in[4] = {v.x, v.y, v.z, v.w};
        float q[4];
        #pragma unroll
        for (int j = 0; j < 4; j++){
            uint32_t b = __float_as_uint(in[j]);
            uint32_t ab = b & 0x7fffffffu;
            int sm = ab ? (int)(0x80u | ((ab >> 16) & 0x7Fu)) : 0;
            int sh = min((int)Egb - (int)(ab >> 23), 31);
            float r = (float)(sm >> sh) * scale;
            q[j] = __uint_as_float(__float_as_uint(r) | (b & 0x80000000u));
        }
        ((__half2*)out)[2*idx]   = __floats2half2_rn(q[0], q[1]);
        ((__half2*)out)[2*idx+1] = __floats2half2_rn(q[2], q[3]);
    }
}

__global__ void f2h_k(const float* __restrict__ x, __half* __restrict__ o, int n4){
    int i = blockIdx.x*blockDim.x + threadIdx.x;
    if (i < n4){
        float4 v = ((const float4*)x)[i];
        ((__half2*)o)[2*i]   = __floats2half2_rn(v.x, v.y);
        ((__half2*)o)[2*i+1] = __floats2half2_rn(v.z, v.w);
    }
}

// C[M,N] = A[M,K]*B[N,K]^T. block 128x128x64, 8 warps (2m x 4n). 3-stage cp.async.
// EPI: 2 = fp32 out (O proj); 3 = fused QKV routing (Q rope*QS, K rope->Kh, V plain->Vh)
#define QSCALE 0.12752551f   // (1/sqrt(128)) * log2(e), folded into Q
template<int EPI>
__global__ __launch_bounds__(256) void gemm_tn(const __half* __restrict__ A, const __half* __restrict__ B,
                                               __half* __restrict__ Ch, __half* __restrict__ Kh,
                                               __half* __restrict__ Vh, float* __restrict__ Cf,
                                               int m_off, int N, int K,
                                               const float* __restrict__ cosp, const float* __restrict__ sinp){
    extern __shared__ __half smem[];
    const int tid = threadIdx.x, lane = tid & 31, warp = tid >> 5;
    const int wm = (warp & 1)*64, wn = (warp >> 1)*32;
    const int bm = m_off + blockIdx.y*128, bn = blockIdx.x*128;
    uint32_t sS = cvta_s(smem);

    auto loadtile = [&](int stage, int k0){
        uint32_t sA = sS + stage*32768, sB = sA + 16384;
        #pragma unroll
        for (int i = 0; i < 4; i++){
            int cid = tid + i*256;
            int row = cid >> 3, ch = cid & 7, sw = ch ^ (row & 7);
            cp16(sA + row*128 + sw*16, A + (size_t)(bm+row)*K + k0 + ch*8);
            cp16(sB + row*128 + sw*16, B + (size_t)(bn+row)*K + k0 + ch*8);
        }
        cp_commit();
    };
    loadtile(0, 0); loadtile(1, 64);

    float acc[4][4][4];
    #pragma unroll
    for (int a=0;a<4;a++) for (int b2=0;b2<4;b2++) for (int c=0;c<4;c++) acc[a][b2][c]=0.f;

    const int nk = K/64;
    int cons = 0;
    for (int kt = 0; kt < nk; kt++){
        if (kt+1 < nk) cp_wait1(); else cp_wait0();
        __syncthreads();
        if (kt+2 < nk){
            int st = cons + 2; if (st >= 3) st -= 3;
            loadtile(st, (kt+2)*64);
        }
        uint32_t baseA = sS + cons*32768, baseB = baseA + 16384;
        #pragma unroll
        for (int ks = 0; ks < 4; ks++){
            uint32_t arg[4][4];
            #pragma unroll
            for (int mi = 0; mi < 4; mi++){
                int row = wm + mi*16 + (lane & 15);
                int col = ks*16 + (lane >> 4)*8;
                ldm4(arg[mi][0],arg[mi][1],arg[mi][2],arg[mi][3],
                     baseA + row*128 + (((col>>3) ^ (row&7))*16));
            }
            uint32_t brg[4][2];
            #pragma unroll
            for (int nj = 0; nj < 2; nj++){
                int g = lane >> 3;
                int row = wn + nj*16 + (g>>1)*8 + (lane & 7);
                int col = ks*16 + (g & 1)*8;
                uint32_t r0,r1,r2,r3;
                ldm4(r0,r1,r2,r3, baseB + row*128 + (((col>>3) ^ (row&7))*16));
                brg[nj*2][0]=r0; brg[nj*2][1]=r1; brg[nj*2+1][0]=r2; brg[nj*2+1][1]=r3;
            }
            #pragma unroll
            for (int mi=0;mi<4;mi++)
                #pragma unroll
                for (int nf=0;nf<4;nf++)
                    mma16816(acc[mi][nf], arg[mi][0],arg[mi][1],arg[mi][2],arg[mi][3],
                             brg[nf][0],brg[nf][1]);
        }
        if (++cons == 3) cons = 0;
    }

    __half* dsth = Ch; int coff = 0; int Nd = DIM; bool rope = true; float vs = 1.f;
    if (EPI == 3){
        if (bn < 4096)      { dsth = Ch; coff = 0;    Nd = DIM; rope = true; vs = QSCALE; }
        else if (bn < 5120) { dsth = Kh; coff = 4096; Nd = KVD; rope = true; }
        else                { dsth = Vh; coff = 5120; Nd = KVD; rope = false; }
    }
    #pragma unroll
    for (int mi=0;mi<4;mi++){
        int r0 = bm + wm + mi*16 + (lane>>2), r1 = r0 + 8;
        #pragma unroll
        for (int nf=0;nf<4;nf++){
            int c0 = bn + wn + nf*8 + 2*(lane&3);
            float v0=acc[mi][nf][0], v1=acc[mi][nf][1], v2=acc[mi][nf][2], v3=acc[mi][nf][3];
            if (EPI == 2){
                Cf[(size_t)r0*N + c0]   = v0; Cf[(size_t)r0*N + c0+1] = v1;
                Cf[(size_t)r1*N + c0]   = v2; Cf[(size_t)r1*N + c0+1] = v3;
            } else {
                int col = c0 - coff;
                if (rope){
                    v0 *= vs; v1 *= vs; v2 *= vs; v3 *= vs;
                    int i0 = (c0 & (HD-1)) >> 1;
                    float cs = cosp[r0*64 + i0], sn = sinp[r0*64 + i0];
                    dsth[(size_t)r0*Nd + col]   = __float2half_rn(v0*cs - v1*sn);
                    dsth[(size_t)r0*Nd + col+1] = __float2half_rn(v0*sn + v1*cs);
                    cs = cosp[r1*64 + i0]; sn = sinp[r1*64 + i0];
                    dsth[(size_t)r1*Nd + col]   = __float2half_rn(v2*cs - v3*sn);
                    dsth[(size_t)r1*Nd + col+1] = __float2half_rn(v2*sn + v3*cs);
                } else {
                    dsth[(size_t)r0*Nd + col]   = __float2half_rn(v0);
                    dsth[(size_t)r0*Nd + col+1] = __float2half_rn(v1);
                    dsth[(size_t)r1*Nd + col]   = __float2half_rn(v2);
                    dsth[(size_t)r1*Nd + col+1] = __float2half_rn(v3);
                }
            }
        }
    }
}

// causal GQA flash attention for qb in [qb_off, qb_off+gridDim.x). Heavy tiles first.
// Q pre-scaled by (1/sqrt(hd))*log2(e): softmax is pure base-2.
__global__ __launch_bounds__(256) void flash_k(const __half* __restrict__ Q, const __half* __restrict__ Kg,
                                               const __half* __restrict__ Vg, __half* __restrict__ O,
                                               int qb_off){
    extern __shared__ __half smemh[];
    __half* Qs = smemh;
    __half* Ks = smemh + 128*128;
    __half* Vs = Ks + 2*64*128;
    const int tid = threadIdx.x, lane = tid & 31, warp = tid >> 5;
    const int qb = qb_off + (gridDim.x - 1 - blockIdx.x);
    const int h = blockIdx.y, kvh = h >> 2;
    uint32_t sQ = cvta_s(Qs), sK = cvta_s(Ks), sV = cvta_s(Vs);

    auto loadKV = [&](int stage, int j){
        const __half* kg = Kg + (size_t)(j*64)*KVD + kvh*HD;
        const __half* vg = Vg + (size_t)(j*64)*KVD + kvh*HD;
        #pragma unroll
        for (int i = 0; i < 4; i++){
            int cid = tid + i*256;
            int row = cid >> 4, ch = cid & 15, sw = ch ^ (row & 7);
            cp16(sK + stage*16384 + row*256 + sw*16, kg + (size_t)row*KVD + ch*8);
            cp16(sV + stage*16384 + row*256 + sw*16, vg + (size_t)row*KVD + ch*8);
        }
        cp_commit();
    };
    const int jmax = 2*qb + 1;
    loadKV(0, 0); loadKV(1, 1);

    {
        const __half* qg = Q + (size_t)(qb*128)*DIM + h*HD;
        #pragma unroll
        for (int i = 0; i < 8; i++){
            int cid = tid + i*256;
            int row = cid >> 4, ch = cid & 15, sw = ch ^ (row & 7);
            *(uint4*)((char*)Qs + row*256 + sw*16) = *(const uint4*)(qg + (size_t)row*DIM + ch*8);
        }
    }

    float o[16][4];
    #pragma unroll
    for (int i=0;i<16;i++){ o[i][0]=0.f;o[i][1]=0.f;o[i][2]=0.f;o[i][3]=0.f; }
    const float NEGINF = __int_as_float(0xff800000);
    float m0 = NEGINF, m1 = NEGINF, l0 = 0.f, l1 = 0.f;
    const int wm = warp*16;
    const int r0g = qb*128 + wm + (lane>>2), r1g = r0g + 8;

    for (int j = 0; j <= jmax; j++){
        if (j < jmax) cp_wait1(); else cp_wait0();
        __syncthreads();
        uint32_t bK = sK + (j&1)*16384, bV = sV + (j&1)*16384;

        float sacc[8][4];
        #pragma unroll
        for (int f=0;f<8;f++){ sacc[f][0]=0.f;sacc[f][1]=0.f;sacc[f][2]=0.f;sacc[f][3]=0.f; }

        #pragma unroll
        for (int ks = 0; ks < 8; ks++){
            int row = wm + (lane & 15);
            int col = ks*16 + (lane >> 4)*8;
            uint32_t a0,a1,a2,a3;
            ldm4(a0,a1,a2,a3, sQ + row*256 + (((col>>3) ^ (row&7))*16));
            #pragma unroll
            for (int nj = 0; nj < 4; nj++){
                int g = lane >> 3;
                int brow = nj*16 + (g>>1)*8 + (lane & 7);
                int bcol = ks*16 + (g & 1)*8;
                uint32_t r0,r1,r2,r3;
                ldm4(r0,r1,r2,r3, bK + brow*256 + (((bcol>>3) ^ (brow&7))*16));
                mma16816(sacc[nj*2],   a0,a1,a2,a3, r0,r1);
                mma16816(sacc[nj*2+1], a0,a1,a2,a3, r2,r3);
            }
        }

        const bool masked = (j >= 2*qb);
        float mx0 = NEGINF, mx1 = NEGINF;
        #pragma unroll
        for (int f = 0; f < 8; f++){
            float v0 = sacc[f][0], v1 = sacc[f][1];
            float v2 = sacc[f][2], v3 = sacc[f][3];
            if (masked){
                int c0 = j*64 + f*8 + 2*(lane & 3);
                if (c0   > r0g) v0 = NEGINF;
                if (c0+1 > r0g) v1 = NEGINF;
                if (c0   > r1g) v2 = NEGINF;
                if (c0+1 > r1g) v3 = NEGINF;
                sacc[f][0]=v0; sacc[f][1]=v1; sacc[f][2]=v2; sacc[f][3]=v3;
            }
            mx0 = fmaxf(mx0, fmaxf(v0, v1));
            mx1 = fmaxf(mx1, fmaxf(v2, v3));
        }
        mx0 = fmaxf(mx0, __shfl_xor_sync(~0u, mx0, 1));
        mx0 = fmaxf(mx0, __shfl_xor_sync(~0u, mx0, 2));
        mx1 = fmaxf(mx1, __shfl_xor_sync(~0u, mx1, 1));
        mx1 = fmaxf(mx1, __shfl_xor_sync(~0u, mx1, 2));
        float nm0 = fmaxf(m0, mx0), nm1 = fmaxf(m1, mx1);
        float al0 = exp2f(m0 - nm0), al1 = exp2f(m1 - nm1);
        m0 = nm0; m1 = nm1;

        float rs0 = 0.f, rs1 = 0.f;
        uint32_t pk[8][2];
        #pragma unroll
        for (int f = 0; f < 8; f++){
            float p0 = exp2f(sacc[f][0]-nm0);
            float p1 = exp2f(sacc[f][1]-nm0);
            float p2 = exp2f(sacc[f][2]-nm1);
            float p3 = exp2f(sacc[f][3]-nm1);
            rs0 += p0 + p1; rs1 += p2 + p3;
            __half2 h01 = __floats2half2_rn(p0, p1);
            __half2 h23 = __floats2half2_rn(p2, p3);
            pk[f][0] = *(uint32_t*)&h01;
            pk[f][1] = *(uint32_t*)&h23;
        }
        rs0 += __shfl_xor_sync(~0u, rs0, 1);
        rs0 += __shfl_xor_sync(~0u, rs0, 2);
        rs1 += __shfl_xor_sync(~0u, rs1, 1);
        rs1 += __shfl_xor_sync(~0u, rs1, 2);
        l0 = l0*al0 + rs0; l1 = l1*al1 + rs1;

        #pragma unroll
        for (int nf=0;nf<16;nf++){
            o[nf][0]*=al0; o[nf][1]*=al0; o[nf][2]*=al1; o[nf][3]*=al1;
        }
        #pragma unroll
        for (int ks = 0; ks < 4; ks++){
            uint32_t a0=pk[2*ks][0], a1=pk[2*ks][1], a2=pk[2*ks+1][0], a3=pk[2*ks+1][1];
            #pragma unroll
            for (int nb = 0; nb < 8; nb++){
                int krow = ks*16 + (lane & 15);
                int ncol = nb*16 + (lane >> 4)*8;
                uint32_t b0,b1,b2,b3;
                ldm4t(b0,b1,b2,b3, bV + krow*256 + (((ncol>>3) ^ (krow&7))*16));
                mma16816(o[2*nb],   a0,a1,a2,a3, b0,b1);
                mma16816(o[2*nb+1], a0,a1,a2,a3, b2,b3);
            }
        }
        __syncthreads();
        if (j+2 <= jmax) loadKV(j&1, j+2);
    }

    float inv0 = 1.f/l0, inv1 = 1.f/l1;
    #pragma unroll
    for (int nf=0;nf<16;nf++){
        int c0 = nf*8 + 2*(lane&3);
        O[(size_t)r0g*DIM + h*HD + c0]   = __float2half_rn(o[nf][0]*inv0);
        O[(size_t)r0g*DIM + h*HD + c0+1] = __float2half_rn(o[nf][1]*inv0);
        O[(size_t)r1g*DIM + h*HD + c0]   = __float2half_rn(o[nf][2]*inv1);
        O[(size_t)r1g*DIM + h*HD + c0+1] = __float2half_rn(o[nf][3]*inv1);
    }
}

extern "C" void kernel_launch(void* const* d_in, const int* in_sizes, int n_in,
                              void* d_out, int out_size) {
    const float* x    = (const float*)d_in[0];
    const float* wq   = (const float*)d_in[1];
    const float* wk   = (const float*)d_in[2];
    const float* wv   = (const float*)d_in[3];
    const float* wo   = (const float*)d_in[4];
    const float* fcos = (const float*)d_in[5];
    const float* fsin = (const float*)d_in[6];

    void *p_wqkv,*p_wo,*p_x,*p_q,*p_kb,*p_vb,*p_at,*p_gm;
    cudaGetSymbolAddress(&p_wqkv, g_wqkv); cudaGetSymbolAddress(&p_wo, g_wo);
    cudaGetSymbolAddress(&p_x,  g_x);  cudaGetSymbolAddress(&p_q,  g_q);
    cudaGetSymbolAddress(&p_kb, g_kb); cudaGetSymbolAddress(&p_vb, g_vb);
    cudaGetSymbolAddress(&p_at, g_at); cudaGetSymbolAddress(&p_gm, g_gmax);
    unsigned* gm = (unsigned*)p_gm;
    __half* hqkv = (__half*)p_wqkv; __half* hwo = (__half*)p_wo;
    __half* hx = (__half*)p_x;  __half* hq = (__half*)p_q;
    __half* hk = (__half*)p_kb; __half* hv = (__half*)p_vb;
    __half* ha = (__half*)p_at;

    cudaFuncSetAttribute(gemm_tn<2>, cudaFuncAttributeMaxDynamicSharedMemorySize, 98304);
    cudaFuncSetAttribute(gemm_tn<3>, cudaFuncAttributeMaxDynamicSharedMemorySize, 98304);
    cudaFuncSetAttribute(flash_k,    cudaFuncAttributeMaxDynamicSharedMemorySize, 98304);

    static cudaStream_t s1 = nullptr, s2 = nullptr, s3 = nullptr;
    static cudaEvent_t e00=nullptr,e1=nullptr,e2=nullptr,e3=nullptr;
    static cudaEvent_t eqlo=nullptr,eqhi=nullptr,eolo=nullptr,eoB=nullptr;
    if (!s1){
        cudaStreamCreateWithFlags(&s1, cudaStreamNonBlocking);
        cudaStreamCreateWithFlags(&s2, cudaStreamNonBlocking);
        cudaStreamCreateWithFlags(&s3, cudaStreamNonBlocking);
        cudaEventCreateWithFlags(&e00, cudaEventDisableTiming);
        cudaEventCreateWithFlags(&e1,  cudaEventDisableTiming);
        cudaEventCreateWithFlags(&e2,  cudaEventDisableTiming);
        cudaEventCreateWithFlags(&e3,  cudaEventDisableTiming);
        cudaEventCreateWithFlags(&eqlo,cudaEventDisableTiming);
        cudaEventCreateWithFlags(&eqhi,cudaEventDisableTiming);
        cudaEventCreateWithFlags(&eolo,cudaEventDisableTiming);
        cudaEventCreateWithFlags(&eoB, cudaEventDisableTiming);
    }

    // ---- prologue: zero, then per-weight gmax+quant on each branch stream ----
    zero_gmax_k<<<1,256>>>(gm);
    cudaEventRecord(e00, 0);

    cudaStreamWaitEvent(s1, e00, 0);
    group_max_w<<<dim3(1,KVD/8),256,0,s1>>>(wk, gm+64);
    quant_k<<<1024,256,0,s1>>>(wk, gm+64, hqkv + (size_t)4096*DIM, KVD*DIM/4, DIM/4);
    cudaEventRecord(e1, s1);

    f2h_k<<<(S_LEN*DIM/4+255)/256,256,0,s2>>>(x, hx, S_LEN*DIM/4);
    cudaStreamWaitEvent(s2, e00, 0);
    group_max_w<<<dim3(1,KVD/8),256,0,s2>>>(wv, gm+128);
    quant_k<<<1024,256,0,s2>>>(wv, gm+128, hqkv + (size_t)5120*DIM, KVD*DIM/4, DIM/4);
    cudaEventRecord(e2, s2);

    cudaStreamWaitEvent(s3, e00, 0);
    group_max_w<<<dim3(1,DIM/8),256,0,s3>>>(wo, gm+192);
    quant_k<<<2048,256,0,s3>>>(wo, gm+192, hwo, DIM*DIM/4, DIM/4);
    cudaEventRecord(e3, s3);

    // default: gmax(wq) -> quant(wq) -> fused QKV GEMM lo/hi
    group_max_w<<<dim3(1,DIM/8),256>>>(wq, gm+0);
    quant_k<<<2048,256>>>(wq, gm+0, hqkv, DIM*DIM/4, DIM/4);
    cudaStreamWaitEvent(0, e1, 0);
    cudaStreamWaitEvent(0, e2, 0);
    gemm_tn<3><<<dim3(48,8),256,98304>>>(hx, hqkv, hq, hk, hv, nullptr,
                                         0, NQKV, DIM, fcos, fsin);
    cudaEventRecord(eqlo, 0);
    gemm_tn<3><<<dim3(48,8),256,98304>>>(hx, hqkv, hq, hk, hv, nullptr,
                                         1024, NQKV, DIM, fcos, fsin);
    cudaEventRecord(eqhi, 0);

    // s1: flash-lo (qb 0..7) -> O rows 0..1023
    cudaStreamWaitEvent(s1, eqlo, 0);
    flash_k<<<dim3(8,32),256,98304,s1>>>(hq, hk, hv, ha, 0);
    cudaStreamWaitEvent(s1, e3, 0);
    gemm_tn<2><<<dim3(32,8),256,98304,s1>>>(ha, hwo, nullptr, nullptr, nullptr, (float*)d_out,
                                            0, DIM, DIM, nullptr, nullptr);
    cudaEventRecord(eolo, s1);

    // s2: flash_B (qb 12..15) concurrent with default's flash_A -> O rows 1536..2047
    cudaStreamWaitEvent(s2, eqhi, 0);
    flash_k<<<dim3(4,32),256,98304,s2>>>(hq, hk, hv, ha, 12);
    cudaStreamWaitEvent(s2, e3, 0);
    gemm_tn<2><<<dim3(32,4),256,98304,s2>>>(ha, hwo, nullptr, nullptr, nullptr, (float*)d_out,
                                            1536, DIM, DIM, nullptr, nullptr);
    cudaEventRecord(eoB, s2);

    // default: flash_A (qb 8..11) -> O rows 1024..1535, then join
    flash_k<<<dim3(4,32),256,98304>>>(hq, hk, hv, ha, 8);
    cudaStreamWaitEvent(0, e3, 0);
    gemm_tn<2><<<dim3(32,4),256,98304>>>(ha, hwo, nullptr, nullptr, nullptr, (float*)d_out,
                                         1024, DIM, DIM, nullptr, nullptr);
    cudaStreamWaitEvent(0, eolo, 0);
    cudaStreamWaitEvent(0, eoB, 0);
}

// round 15
// speedup vs baseline: 1.0697x; 1.0288x over previous
#include <cuda_runtime.h>
#include <cuda_fp16.h>
#include <cstdint>

#define S_LEN 2048
#define DIM   4096
#define HD    128
#define KVD   1024
#define NQKV  6144

__device__ __half g_wqkv[NQKV*DIM];   // rows 0..4095 wq, 4096..5119 wk, 5120..6143 wv
__device__ __half g_wo[DIM*DIM];
__device__ __half g_x [S_LEN*DIM];
__device__ __half g_q [S_LEN*DIM];
__device__ __half g_kb[S_LEN*KVD];
__device__ __half g_vb[S_LEN*KVD];
__device__ __half g_at[S_LEN*DIM];
__device__ unsigned g_gmax[4*64];

__device__ __forceinline__ uint32_t cvta_s(const void* p){
    return (uint32_t)__cvta_generic_to_shared(p);
}
__device__ __forceinline__ void cp16(uint32_t s, const void* g){
    asm volatile("cp.async.cg.shared.global [%0], [%1], 16;\n" :: "r"(s), "l"(g));
}
__device__ __forceinline__ void cp_commit(){ asm volatile("cp.async.commit_group;\n"); }
__device__ __forceinline__ void cp_wait1(){ asm volatile("cp.async.wait_group 1;\n"); }
__device__ __forceinline__ void cp_wait0(){ asm volatile("cp.async.wait_group 0;\n"); }
__device__ __forceinline__ void ldm4(uint32_t& a,uint32_t& b,uint32_t& c,uint32_t& d, uint32_t addr){
    asm volatile("ldmatrix.sync.aligned.m8n8.x4.shared.b16 {%0,%1,%2,%3},[%4];\n"
                 : "=r"(a),"=r"(b),"=r"(c),"=r"(d) : "r"(addr));
}
__device__ __forceinline__ void ldm4t(uint32_t& a,uint32_t& b,uint32_t& c,uint32_t& d, uint32_t addr){
    asm volatile("ldmatrix.sync.aligned.m8n8.x4.trans.shared.b16 {%0,%1,%2,%3},[%4];\n"
                 : "=r"(a),"=r"(b),"=r"(c),"=r"(d) : "r"(addr));
}
__device__ __forceinline__ void mma16816(float* c, uint32_t a0,uint32_t a1,uint32_t a2,uint32_t a3,
                                         uint32_t b0,uint32_t b1){
    asm volatile("mma.sync.aligned.m16n8k16.row.col.f32.f16.f16.f32 "
                 "{%0,%1,%2,%3},{%4,%5,%6,%7},{%8,%9},{%0,%1,%2,%3};\n"
                 : "+f"(c[0]),"+f"(c[1]),"+f"(c[2]),"+f"(c[3])
                 : "r"(a0),"r"(a1),"r"(a2),"r"(a3),"r"(b0),"r"(b1));
}

// ---------------- quantization ----------------
__global__ void zero_gmax_k(unsigned* gm){ gm[threadIdx.x] = 0u; }

__global__ __launch_bounds__(256) void group_max_w(const float* __restrict__ W,
                                                   unsigned* __restrict__ gm){
    const float4* base = (const float4*)W + (size_t)blockIdx.y*8*1024 + threadIdx.x;
    unsigned m[4] = {0,0,0,0};
    #pragma unroll
    for (int r = 0; r < 8; r++){
        #pragma unroll
        for (int i = 0; i < 4; i++){
            float4 v = base[(size_t)r*1024 + i*256];
            unsigned b0 = __float_as_uint(v.x) & 0x7fffffffu;
            unsigned b1 = __float_as_uint(v.y) & 0x7fffffffu;
            unsigned b2 = __float_as_uint(v.z) & 0x7fffffffu;
            unsigned b3 = __float_as_uint(v.w) & 0x7fffffffu;
            m[i] = max(m[i], max(max(b0,b1), max(b2,b3)));
        }
    }
    __shared__ unsigned red[64];
    if (threadIdx.x < 64) red[threadIdx.x] = 0u;
    __syncthreads();
    #pragma unroll
    for (int i = 0; i < 4; i++)
        atomicMax(&red[(threadIdx.x + i*256) >> 4], m[i]);
    __syncthreads();
    if (threadIdx.x < 64) atomicMax(&gm[threadIdx.x], red[threadIdx.x]);
}

__global__ __launch_bounds__(256) void quant_k(const float* __restrict__ W,
                                               const unsigned* __restrict__ gm,
                                               __half* __restrict__ out, int n4, int cols4){
    for (int idx = blockIdx.x*blockDim.x + threadIdx.x; idx < n4; idx += gridDim.x*blockDim.x){
        float4 v = ((const float4*)W)[idx];
        unsigned Egb = gm[(idx % cols4) >> 4] >> 23;
        float scale = __uint_as_float((Egb - 7u) << 23);
        float in[4] = {v.x, v.y, v.z, v.w};
        float q[4];
        #pragma unroll
        for (int j = 0; j < 4; j++){
            uint32_t b = __float_as_uint(in[j]);
            uint32_t ab = b & 0x7fffffffu;
            int sm = ab ? (int)(0x80u | ((ab >> 16) & 0x7Fu)) : 0;
            int sh = min((int)Egb - (int)(ab >> 23), 31);
            float r = (float)(sm >> sh) * scale;
            q[j] = __uint_as_float(__float_as_uint(r) | (b & 0x80000000u));
        }
        ((__half2*)out)[2*idx]   = __floats2half2_rn(q[0], q[1]);
        ((__half2*)out)[2*idx+1] = __floats2half2_rn(q[2], q[3]);
    }
}

__global__ void f2h_k(const float* __restrict__ x, __half* __restrict__ o, int n4){
    int i = blockIdx.x*blockDim.x + threadIdx.x;
    if (i < n4){
        float4 v = ((const float4*)x)[i];
        ((__half2*)o)[2*i]   = __floats2half2_rn(v.x, v.y);
        ((__half2*)o)[2*i+1] = __floats2half2_rn(v.z, v.w);
    }
}

// C[M,N] = A[M,K]*B[N,K]^T. block 128x128x64, 8 warps (2m x 4n). 3-stage cp.async.
// EPI: 2 = fp32 out (O proj); 3 = fused QKV routing (Q rope*QS, K rope->Kh, V plain->Vh)
// n_off: column offset (CTA x covers bn = n_off + bx*128)
#define QSCALE 0.12752551f   // (1/sqrt(128)) * log2(e), folded into Q
template<int EPI>
__global__ __launch_bounds__(256) void gemm_tn(const __half* __restrict__ A, const __half* __restrict__ B,
                                               __half* __restrict__ Ch, __half* __restrict__ Kh,
                                               __half* __restrict__ Vh, float* __restrict__ Cf,
                                               int m_off, int n_off, int N, int K,
                                               const float* __restrict__ cosp, const float* __restrict__ sinp){
    extern __shared__ __half smem[];
    const int tid = threadIdx.x, lane = tid & 31, warp = tid >> 5;
    const int wm = (warp & 1)*64, wn = (warp >> 1)*32;
    const int bm = m_off + blockIdx.y*128, bn = n_off + blockIdx.x*128;
    uint32_t sS = cvta_s(smem);

    auto loadtile = [&](int stage, int k0){
        uint32_t sA = sS + stage*32768, sB = sA + 16384;
        #pragma unroll
        for (int i = 0; i < 4; i++){
            int cid = tid + i*256;
            int row = cid >> 3, ch = cid & 7, sw = ch ^ (row & 7);
            cp16(sA + row*128 + sw*16, A + (size_t)(bm+row)*K + k0 + ch*8);
            cp16(sB + row*128 + sw*16, B + (size_t)(bn+row)*K + k0 + ch*8);
        }
        cp_commit();
    };
    loadtile(0, 0); loadtile(1, 64);

    float acc[4][4][4];
    #pragma unroll
    for (int a=0;a<4;a++) for (int b2=0;b2<4;b2++) for (int c=0;c<4;c++) acc[a][b2][c]=0.f;

    const int nk = K/64;
    int cons = 0;
    for (int kt = 0; kt < nk; kt++){
        if (kt+1 < nk) cp_wait1(); else cp_wait0();
        __syncthreads();
        if (kt+2 < nk){
            int st = cons + 2; if (st >= 3) st -= 3;
            loadtile(st, (kt+2)*64);
        }
        uint32_t baseA = sS + cons*32768, baseB = baseA + 16384;
        #pragma unroll
        for (int ks = 0; ks < 4; ks++){
            uint32_t arg[4][4];
            #pragma unroll
            for (int mi = 0; mi < 4; mi++){
                int row = wm + mi*16 + (lane & 15);
                int col = ks*16 + (lane >> 4)*8;
                ldm4(arg[mi][0],arg[mi][1],arg[mi][2],arg[mi][3],
                     baseA + row*128 + (((col>>3) ^ (row&7))*16));
            }
            uint32_t brg[4][2];
            #pragma unroll
            for (int nj = 0; nj < 2; nj++){
                int g = lane >> 3;
                int row = wn + nj*16 + (g>>1)*8 + (lane & 7);
                int col = ks*16 + (g & 1)*8;
                uint32_t r0,r1,r2,r3;
                ldm4(r0,r1,r2,r3, baseB + row*128 + (((col>>3) ^ (row&7))*16));
                brg[nj*2][0]=r0; brg[nj*2][1]=r1; brg[nj*2+1][0]=r2; brg[nj*2+1][1]=r3;
            }
            #pragma unroll
            for (int mi=0;mi<4;mi++)
                #pragma unroll
                for (int nf=0;nf<4;nf++)
                    mma16816(acc[mi][nf], arg[mi][0],arg[mi][1],arg[mi][2],arg[mi][3],
                             brg[nf][0],brg[nf][1]);
        }
        if (++cons == 3) cons = 0;
    }

    __half* dsth = Ch; int coff = 0; int Nd = DIM; bool rope = true; float vs = 1.f;
    if (EPI == 3){
        if (bn < 4096)      { dsth = Ch; coff = 0;    Nd = DIM; rope = true; vs = QSCALE; }
        else if (bn < 5120) { dsth = Kh; coff = 4096; Nd = KVD; rope = true; }
        else                { dsth = Vh; coff = 5120; Nd = KVD; rope = false; }
    }
    #pragma unroll
    for (int mi=0;mi<4;mi++){
        int r0 = bm + wm + mi*16 + (lane>>2), r1 = r0 + 8;
        #pragma unroll
        for (int nf=0;nf<4;nf++){
            int c0 = bn + wn + nf*8 + 2*(lane&3);
            float v0=acc[mi][nf][0], v1=acc[mi][nf][1], v2=acc[mi][nf][2], v3=acc[mi][nf][3];
            if (EPI == 2){
                float2 a01 = make_float2(v0, v1), a23 = make_float2(v2, v3);
                *(float2*)(Cf + (size_t)r0*N + c0) = a01;
                *(float2*)(Cf + (size_t)r1*N + c0) = a23;
            } else {
                int col = c0 - coff;
                if (rope){
                    v0 *= vs; v1 *= vs; v2 *= vs; v3 *= vs;
                    int i0 = (c0 & (HD-1)) >> 1;
                    float cs = cosp[r0*64 + i0], sn = sinp[r0*64 + i0];
                    dsth[(size_t)r0*Nd + col]   = __float2half_rn(v0*cs - v1*sn);
                    dsth[(size_t)r0*Nd + col+1] = __float2half_rn(v0*sn + v1*cs);
                    cs = cosp[r1*64 + i0]; sn = sinp[r1*64 + i0];
                    dsth[(size_t)r1*Nd + col]   = __float2half_rn(v2*cs - v3*sn);
                    dsth[(size_t)r1*Nd + col+1] = __float2half_rn(v2*sn + v3*cs);
                } else {
                    dsth[(size_t)r0*Nd + col]   = __float2half_rn(v0);
                    dsth[(size_t)r0*Nd + col+1] = __float2half_rn(v1);
                    dsth[(size_t)r1*Nd + col]   = __float2half_rn(v2);
                    dsth[(size_t)r1*Nd + col+1] = __float2half_rn(v3);
                }
            }
        }
    }
}

// causal GQA flash attention for qb in [qb_off, qb_off+gridDim.x). Heavy tiles first.
// Q pre-scaled by (1/sqrt(hd))*log2(e): softmax is pure base-2.
__global__ __launch_bounds__(256) void flash_k(const __half* __restrict__ Q, const __half* __restrict__ Kg,
                                               const __half* __restrict__ Vg, __half* __restrict__ O,
                                               int qb_off){
    extern __shared__ __half smemh[];
    __half* Qs = smemh;
    __half* Ks = smemh + 128*128;
    __half* Vs = Ks + 2*64*128;
    const int tid = threadIdx.x, lane = tid & 31, warp = tid >> 5;
    const int qb = qb_off + (gridDim.x - 1 - blockIdx.x);
    const int h = blockIdx.y, kvh = h >> 2;
    uint32_t sQ = cvta_s(Qs), sK = cvta_s(Ks), sV = cvta_s(Vs);

    auto loadKV = [&](int stage, int j){
        const __half* kg = Kg + (size_t)(j*64)*KVD + kvh*HD;
        const __half* vg = Vg + (size_t)(j*64)*KVD + kvh*HD;
        #pragma unroll
        for (int i = 0; i < 4; i++){
            int cid = tid + i*256;
            int row = cid >> 4, ch = cid & 15, sw = ch ^ (row & 7);
            cp16(sK + stage*16384 + row*256 + sw*16, kg + (size_t)row*KVD + ch*8);
            cp16(sV + stage*16384 + row*256 + sw*16, vg + (size_t)row*KVD + ch*8);
        }
        cp_commit();
    };
    const int jmax = 2*qb + 1;
    loadKV(0, 0); loadKV(1, 1);

    {
        const __half* qg = Q + (size_t)(qb*128)*DIM + h*HD;
        #pragma unroll
        for (int i = 0; i < 8; i++){
            int cid = tid + i*256;
            int row = cid >> 4, ch = cid & 15, sw = ch ^ (row & 7);
            *(uint4*)((char*)Qs + row*256 + sw*16) = *(const uint4*)(qg + (size_t)row*DIM + ch*8);
        }
    }

    float o[16][4];
    #pragma unroll
    for (int i=0;i<16;i++){ o[i][0]=0.f;o[i][1]=0.f;o[i][2]=0.f;o[i][3]=0.f; }
    const float NEGINF = __int_as_float(0xff800000);
    float m0 = NEGINF, m1 = NEGINF, l0 = 0.f, l1 = 0.f;
    const int wm = warp*16;
    const int r0g = qb*128 + wm + (lane>>2), r1g = r0g + 8;

    for (int j = 0; j <= jmax; j++){
        if (j < jmax) cp_wait1(); else cp_wait0();
        __syncthreads();
        uint32_t bK = sK + (j&1)*16384, bV = sV + (j&1)*16384;

        float sacc[8][4];
        #pragma unroll
        for (int f=0;f<8;f++){ sacc[f][0]=0.f;sacc[f][1]=0.f;sacc[f][2]=0.f;sacc[f][3]=0.f; }

        #pragma unroll
        for (int ks = 0; ks < 8; ks++){
            int row = wm + (lane & 15);
            int col = ks*16 + (lane >> 4)*8;
            uint32_t a0,a1,a2,a3;
            ldm4(a0,a1,a2,a3, sQ + row*256 + (((col>>3) ^ (row&7))*16));
            #pragma unroll
            for (int nj = 0; nj < 4; nj++){
                int g = lane >> 3;
                int brow = nj*16 + (g>>1)*8 + (lane & 7);
                int bcol = ks*16 + (g & 1)*8;
                uint32_t r0,r1,r2,r3;
                ldm4(r0,r1,r2,r3, bK + brow*256 + (((bcol>>3) ^ (brow&7))*16));
                mma16816(sacc[nj*2],   a0,a1,a2,a3, r0,r1);
                mma16816(sacc[nj*2+1], a0,a1,a2,a3, r2,r3);
            }
        }

        const bool masked = (j >= 2*qb);
        float mx0 = NEGINF, mx1 = NEGINF;
        #pragma unroll
        for (int f = 0; f < 8; f++){
            float v0 = sacc[f][0], v1 = sacc[f][1];
            float v2 = sacc[f][2], v3 = sacc[f][3];
            if (masked){
                int c0 = j*64 + f*8 + 2*(lane & 3);
                if (c0   > r0g) v0 = NEGINF;
                if (c0+1 > r0g) v1 = NEGINF;
                if (c0   > r1g) v2 = NEGINF;
                if (c0+1 > r1g) v3 = NEGINF;
                sacc[f][0]=v0; sacc[f][1]=v1; sacc[f][2]=v2; sacc[f][3]=v3;
            }
            mx0 = fmaxf(mx0, fmaxf(v0, v1));
            mx1 = fmaxf(mx1, fmaxf(v2, v3));
        }
        mx0 = fmaxf(mx0, __shfl_xor_sync(~0u, mx0, 1));
        mx0 = fmaxf(mx0, __shfl_xor_sync(~0u, mx0, 2));
        mx1 = fmaxf(mx1, __shfl_xor_sync(~0u, mx1, 1));
        mx1 = fmaxf(mx1, __shfl_xor_sync(~0u, mx1, 2));
        float nm0 = fmaxf(m0, mx0), nm1 = fmaxf(m1, mx1);
        float al0 = exp2f(m0 - nm0), al1 = exp2f(m1 - nm1);
        m0 = nm0; m1 = nm1;

        float rs0 = 0.f, rs1 = 0.f;
        uint32_t pk[8][2];
        #pragma unroll
        for (int f = 0; f < 8; f++){
            float p0 = exp2f(sacc[f][0]-nm0);
            float p1 = exp2f(sacc[f][1]-nm0);
            float p2 = exp2f(sacc[f][2]-nm1);
            float p3 = exp2f(sacc[f][3]-nm1);
            rs0 += p0 + p1; rs1 += p2 + p3;
            __half2 h01 = __floats2half2_rn(p0, p1);
            __half2 h23 = __floats2half2_rn(p2, p3);
            pk[f][0] = *(uint32_t*)&h01;
            pk[f][1] = *(uint32_t*)&h23;
        }
        rs0 += __shfl_xor_sync(~0u, rs0, 1);
        rs0 += __shfl_xor_sync(~0u, rs0, 2);
        rs1 += __shfl_xor_sync(~0u, rs1, 1);
        rs1 += __shfl_xor_sync(~0u, rs1, 2);
        l0 = l0*al0 + rs0; l1 = l1*al1 + rs1;

        #pragma unroll
        for (int nf=0;nf<16;nf++){
            o[nf][0]*=al0; o[nf][1]*=al0; o[nf][2]*=al1; o[nf][3]*=al1;
        }
        #pragma unroll
        for (int ks = 0; ks < 4; ks++){
            uint32_t a0=pk[2*ks][0], a1=pk[2*ks][1], a2=pk[2*ks+1][0], a3=pk[2*ks+1][1];
            #pragma unroll
            for (int nb = 0; nb < 8; nb++){
                int krow = ks*16 + (lane & 15);
                int ncol = nb*16 + (lane >> 4)*8;
                uint32_t b0,b1,b2,b3;
                ldm4t(b0,b1,b2,b3, bV + krow*256 + (((ncol>>3) ^ (krow&7))*16));
                mma16816(o[2*nb],   a0,a1,a2,a3, b0,b1);
                mma16816(o[2*nb+1], a0,a1,a2,a3, b2,b3);
            }
        }
        __syncthreads();
        if (j+2 <= jmax) loadKV(j&1, j+2);
    }

    float inv0 = 1.f/l0, inv1 = 1.f/l1;
    #pragma unroll
    for (int nf=0;nf<16;nf++){
        int c0 = nf*8 + 2*(lane&3);
        O[(size_t)r0g*DIM + h*HD + c0]   = __float2half_rn(o[nf][0]*inv0);
        O[(size_t)r0g*DIM + h*HD + c0+1] = __float2half_rn(o[nf][1]*inv0);
        O[(size_t)r1g*DIM + h*HD + c0]   = __float2half_rn(o[nf][2]*inv1);
        O[(size_t)r1g*DIM + h*HD + c0+1] = __float2half_rn(o[nf][3]*inv1);
    }
}

extern "C" void kernel_launch(void* const* d_in, const int* in_sizes, int n_in,
                              void* d_out, int out_size) {
    const float* x    = (const float*)d_in[0];
    const float* wq   = (const float*)d_in[1];
    const float* wk   = (const float*)d_in[2];
    const float* wv   = (const float*)d_in[3];
    const float* wo   = (const float*)d_in[4];
    const float* fcos = (const float*)d_in[5];
    const float* fsin = (const float*)d_in[6];

    void *p_wqkv,*p_wo,*p_x,*p_q,*p_kb,*p_vb,*p_at,*p_gm;
    cudaGetSymbolAddress(&p_wqkv, g_wqkv); cudaGetSymbolAddress(&p_wo, g_wo);
    cudaGetSymbolAddress(&p_x,  g_x);  cudaGetSymbolAddress(&p_q,  g_q);
    cudaGetSymbolAddress(&p_kb, g_kb); cudaGetSymbolAddress(&p_vb, g_vb);
    cudaGetSymbolAddress(&p_at, g_at); cudaGetSymbolAddress(&p_gm, g_gmax);
    unsigned* gm = (unsigned*)p_gm;
    __half* hqkv = (__half*)p_wqkv; __half* hwo = (__half*)p_wo;
    __half* hx = (__half*)p_x;  __half* hq = (__half*)p_q;
    __half* hk = (__half*)p_kb; __half* hv = (__half*)p_vb;
    __half* ha = (__half*)p_at;

    cudaFuncSetAttribute(gemm_tn<2>, cudaFuncAttributeMaxDynamicSharedMemorySize, 98304);
    cudaFuncSetAttribute(gemm_tn<3>, cudaFuncAttributeMaxDynamicSharedMemorySize, 98304);
    cudaFuncSetAttribute(flash_k,    cudaFuncAttributeMaxDynamicSharedMemorySize, 98304);

    static cudaStream_t s1 = nullptr, s2 = nullptr, s3 = nullptr;
    static cudaEvent_t e00=nullptr,e1=nullptr,e2=nullptr,e3=nullptr,ef2h=nullptr;
    static cudaEvent_t eAlo=nullptr,eAhi=nullptr,eBlo=nullptr,eBhi=nullptr;
    static cudaEvent_t eolo=nullptr,eoB=nullptr;
    if (!s1){
        cudaStreamCreateWithFlags(&s1, cudaStreamNonBlocking);
        cudaStreamCreateWithFlags(&s2, cudaStreamNonBlocking);
        cudaStreamCreateWithFlags(&s3, cudaStreamNonBlocking);
        cudaEventCreateWithFlags(&e00, cudaEventDisableTiming);
        cudaEventCreateWithFlags(&e1,  cudaEventDisableTiming);
        cudaEventCreateWithFlags(&e2,  cudaEventDisableTiming);
        cudaEventCreateWithFlags(&e3,  cudaEventDisableTiming);
        cudaEventCreateWithFlags(&ef2h,cudaEventDisableTiming);
        cudaEventCreateWithFlags(&eAlo,cudaEventDisableTiming);
        cudaEventCreateWithFlags(&eAhi,cudaEventDisableTiming);
        cudaEventCreateWithFlags(&eBlo,cudaEventDisableTiming);
        cudaEventCreateWithFlags(&eBhi,cudaEventDisableTiming);
        cudaEventCreateWithFlags(&eolo,cudaEventDisableTiming);
        cudaEventCreateWithFlags(&eoB, cudaEventDisableTiming);
    }

    // ---- prologue: zero on default; ALL side streams join capture via e00 first ----
    zero_gmax_k<<<1,256>>>(gm);
    cudaEventRecord(e00, 0);

    cudaStreamWaitEvent(s1, e00, 0);
    group_max_w<<<dim3(1,KVD/8),256,0,s1>>>(wk, gm+64);
    quant_k<<<1024,256,0,s1>>>(wk, gm+64, hqkv + (size_t)4096*DIM, KVD*DIM/4, DIM/4);
    cudaEventRecord(e1, s1);

    cudaStreamWaitEvent(s2, e00, 0);
    f2h_k<<<(S_LEN*DIM/4+255)/256,256,0,s2>>>(x, hx, S_LEN*DIM/4);
    cudaEventRecord(ef2h, s2);
    group_max_w<<<dim3(1,KVD/8),256,0,s2>>>(wv, gm+128);
    quant_k<<<1024,256,0,s2>>>(wv, gm+128, hqkv + (size_t)5120*DIM, KVD*DIM/4, DIM/4);
    cudaEventRecord(e2, s2);

    cudaStreamWaitEvent(s3, e00, 0);
    group_max_w<<<dim3(1,DIM/8),256,0,s3>>>(wo, gm+192);
    quant_k<<<2048,256,0,s3>>>(wo, gm+192, hwo, DIM*DIM/4, DIM/4);
    cudaEventRecord(e3, s3);

    // ---- default: wq path -> QKV A-chunk (N 0..4095), lo then hi ----
    group_max_w<<<dim3(1,DIM/8),256>>>(wq, gm+0);
    quant_k<<<2048,256>>>(wq, gm+0, hqkv, DIM*DIM/4, DIM/4);
    cudaStreamWaitEvent(0, ef2h, 0);
    gemm_tn<3><<<dim3(32,8),256,98304>>>(hx, hqkv, hq, hk, hv, nullptr,
                                         0, 0, NQKV, DIM, fcos, fsin);
    cudaEventRecord(eAlo, 0);
    gemm_tn<3><<<dim3(32,8),256,98304>>>(hx, hqkv, hq, hk, hv, nullptr,
                                         1024, 0, NQKV, DIM, fcos, fsin);
    cudaEventRecord(eAhi, 0);

    // ---- s2: QKV B-chunk (N 4096..6143, wk+wv), lo then hi (f2h/wv stream-ordered) ----
    cudaStreamWaitEvent(s2, e1, 0);
    gemm_tn<3><<<dim3(16,8),256,98304,s2>>>(hx, hqkv, hq, hk, hv, nullptr,
                                            0, 4096, NQKV, DIM, fcos, fsin);
    cudaEventRecord(eBlo, s2);
    gemm_tn<3><<<dim3(16,8),256,98304,s2>>>(hx, hqkv, hq, hk, hv, nullptr,
                                            1024, 4096, NQKV, DIM, fcos, fsin);
    cudaEventRecord(eBhi, s2);

    // ---- s1: flash-lo (qb 0..7) -> O rows 0..1023 ----
    cudaStreamWaitEvent(s1, eAlo, 0);
    cudaStreamWaitEvent(s1, eBlo, 0);
    flash_k<<<dim3(8,32),256,98304,s1>>>(hq, hk, hv, ha, 0);
    cudaStreamWaitEvent(s1, e3, 0);
    gemm_tn<2><<<dim3(32,8),256,98304,s1>>>(ha, hwo, nullptr, nullptr, nullptr, (float*)d_out,
                                            0, 0, DIM, DIM, nullptr, nullptr);
    cudaEventRecord(eolo, s1);

    // ---- s2: flash_B (qb 12..15) -> O rows 1536..2047 (needs A-hi; B-hi stream-ordered) ----
    cudaStreamWaitEvent(s2, eAhi, 0);
    flash_k<<<dim3(4,32),256,98304,s2>>>(hq, hk, hv, ha, 12);
    cudaStreamWaitEvent(s2, e3, 0);
    gemm_tn<2><<<dim3(32,4),256,98304,s2>>>(ha, hwo, nullptr, nullptr, nullptr, (float*)d_out,
                                            1536, 0, DIM, DIM, nullptr, nullptr);
    cudaEventRecord(eoB, s2);

    // ---- default: flash_A (qb 8..11) -> O rows 1024..1535, then join ----
    cudaStreamWaitEvent(0, eBhi, 0);
    flash_k<<<dim3(4,32),256,98304>>>(hq, hk, hv, ha, 8);
    cudaStreamWaitEvent(0, e3, 0);
    gemm_tn<2><<<dim3(32,4),256,98304>>>(ha, hwo, nullptr, nullptr, nullptr, (float*)d_out,
                                         1024, 0, DIM, DIM, nullptr, nullptr);
    cudaStreamWaitEvent(0, eolo, 0);
    cudaStreamWaitEvent(0, eoB, 0);
}

// round 16
// speedup vs baseline: 1.0698x; 1.0001x over previous
#include <cuda_runtime.h>
#include <cuda_fp16.h>
#include <cstdint>

#define S_LEN 2048
#define DIM   4096
#define HD    128
#define KVD   1024
#define NQKV  6144

__device__ __half g_wqkv[NQKV*DIM];   // rows 0..4095 wq, 4096..5119 wk, 5120..6143 wv
__device__ __half g_wo[DIM*DIM];
__device__ __half g_x [S_LEN*DIM];
__device__ __half g_q [S_LEN*DIM];
__device__ __half g_kb[S_LEN*KVD];
__device__ __half g_vb[S_LEN*KVD];
__device__ __half g_at[S_LEN*DIM];
__device__ unsigned g_gmax[4*64];

__device__ __forceinline__ uint32_t cvta_s(const void* p){
    return (uint32_t)__cvta_generic_to_shared(p);
}
__device__ __forceinline__ void cp16(uint32_t s, const void* g){
    asm volatile("cp.async.cg.shared.global [%0], [%1], 16;\n" :: "r"(s), "l"(g));
}
__device__ __forceinline__ void cp_commit(){ asm volatile("cp.async.commit_group;\n"); }
__device__ __forceinline__ void cp_wait1(){ asm volatile("cp.async.wait_group 1;\n"); }
__device__ __forceinline__ void cp_wait0(){ asm volatile("cp.async.wait_group 0;\n"); }
__device__ __forceinline__ void ldm4(uint32_t& a,uint32_t& b,uint32_t& c,uint32_t& d, uint32_t addr){
    asm volatile("ldmatrix.sync.aligned.m8n8.x4.shared.b16 {%0,%1,%2,%3},[%4];\n"
                 : "=r"(a),"=r"(b),"=r"(c),"=r"(d) : "r"(addr));
}
__device__ __forceinline__ void ldm4t(uint32_t& a,uint32_t& b,uint32_t& c,uint32_t& d, uint32_t addr){
    asm volatile("ldmatrix.sync.aligned.m8n8.x4.trans.shared.b16 {%0,%1,%2,%3},[%4];\n"
                 : "=r"(a),"=r"(b),"=r"(c),"=r"(d) : "r"(addr));
}
__device__ __forceinline__ void mma16816(float* c, uint32_t a0,uint32_t a1,uint32_t a2,uint32_t a3,
                                         uint32_t b0,uint32_t b1){
    asm volatile("mma.sync.aligned.m16n8k16.row.col.f32.f16.f16.f32 "
                 "{%0,%1,%2,%3},{%4,%5,%6,%7},{%8,%9},{%0,%1,%2,%3};\n"
                 : "+f"(c[0]),"+f"(c[1]),"+f"(c[2]),"+f"(c[3])
                 : "r"(a0),"r"(a1),"r"(a2),"r"(a3),"r"(b0),"r"(b1));
}

// ---------------- quantization ----------------
__global__ void zero_gmax_k(unsigned* gm){ gm[threadIdx.x] = 0u; }

__global__ __launch_bounds__(256) void group_max_w(const float* __restrict__ W,
                                                   unsigned* __restrict__ gm){
    const float4* base = (const float4*)W + (size_t)blockIdx.y*8*1024 + threadIdx.x;
    unsigned m[4] = {0,0,0,0};
    #pragma unroll
    for (int r = 0; r < 8; r++){
        #pragma unroll
        for (int i = 0; i < 4; i++){
            float4 v = base[(size_t)r*1024 + i*256];
            unsigned b0 = __float_as_uint(v.x) & 0x7fffffffu;
            unsigned b1 = __float_as_uint(v.y) & 0x7fffffffu;
            unsigned b2 = __float_as_uint(v.z) & 0x7fffffffu;
            unsigned b3 = __float_as_uint(v.w) & 0x7fffffffu;
            m[i] = max(m[i], max(max(b0,b1), max(b2,b3)));
        }
    }
    __shared__ unsigned red[64];
    if (threadIdx.x < 64) red[threadIdx.x] = 0u;
    __syncthreads();
    #pragma unroll
    for (int i = 0; i < 4; i++)
        atomicMax(&red[(threadIdx.x + i*256) >> 4], m[i]);
    __syncthreads();
    if (threadIdx.x < 64) atomicMax(&gm[threadIdx.x], red[threadIdx.x]);
}

// sh clamp at 31 maps ab==0 to (0x80>>31)==0, so no zero-select is needed.
__global__ __launch_bounds__(256) void quant_k(const float* __restrict__ W,
                                               const unsigned* __restrict__ gm,
                                               __half* __restrict__ out, int n4, int cols4){
    for (int idx = blockIdx.x*blockDim.x + threadIdx.x; idx < n4; idx += gridDim.x*blockDim.x){
        float4 v = ((const float4*)W)[idx];
        unsigned Egb = gm[(idx % cols4) >> 4] >> 23;
        float scale = __uint_as_float((Egb - 7u) << 23);
        float in[4] = {v.x, v.y, v.z, v.w};
        float q[4];
        #pragma unroll
        for (int j = 0; j < 4; j++){
            uint32_t b = __float_as_uint(in[j]);
            uint32_t ab = b & 0x7fffffffu;
            int sm = (int)(0x80u | ((ab >> 16) & 0x7Fu));
            int sh = min((int)Egb - (int)(ab >> 23), 31);
            float r = (float)(sm >> sh) * scale;
            q[j] = __uint_as_float(__float_as_uint(r) | (b & 0x80000000u));
        }
        ((__half2*)out)[2*idx]   = __floats2half2_rn(q[0], q[1]);
        ((__half2*)out)[2*idx+1] = __floats2half2_rn(q[2], q[3]);
    }
}

__global__ void f2h_k(const float* __restrict__ x, __half* __restrict__ o, int n4){
    int i = blockIdx.x*blockDim.x + threadIdx.x;
    if (i < n4){
        float4 v = ((const float4*)x)[i];
        ((__half2*)o)[2*i]   = __floats2half2_rn(v.x, v.y);
        ((__half2*)o)[2*i+1] = __floats2half2_rn(v.z, v.w);
    }
}

// C[M,N] = A[M,K]*B[N,K]^T. block 128x128x64, 8 warps (2m x 4n). 3-stage cp.async.
// EPI: 2 = fp32 out (O proj); 3 = fused QKV routing (Q rope*QS, K rope->Kh, V plain->Vh)
#define QSCALE 0.12752551f   // (1/sqrt(128)) * log2(e), folded into Q
template<int EPI>
__global__ __launch_bounds__(256) void gemm_tn(const __half* __restrict__ A, const __half* __restrict__ B,
                                               __half* __restrict__ Ch, __half* __restrict__ Kh,
                                               __half* __restrict__ Vh, float* __restrict__ Cf,
                                               int m_off, int n_off, int N, int K,
                                               const float* __restrict__ cosp, const float* __restrict__ sinp){
    extern __shared__ __half smem[];
    const int tid = threadIdx.x, lane = tid & 31, warp = tid >> 5;
    const int wm = (warp & 1)*64, wn = (warp >> 1)*32;
    const int bm = m_off + blockIdx.y*128, bn = n_off + blockIdx.x*128;
    uint32_t sS = cvta_s(smem);

    auto loadtile = [&](int stage, int k0){
        uint32_t sA = sS + stage*32768, sB = sA + 16384;
        #pragma unroll
        for (int i = 0; i < 4; i++){
            int cid = tid + i*256;
            int row = cid >> 3, ch = cid & 7, sw = ch ^ (row & 7);
            cp16(sA + row*128 + sw*16, A + (size_t)(bm+row)*K + k0 + ch*8);
            cp16(sB + row*128 + sw*16, B + (size_t)(bn+row)*K + k0 + ch*8);
        }
        cp_commit();
    };
    loadtile(0, 0); loadtile(1, 64);

    float acc[4][4][4];
    #pragma unroll
    for (int a=0;a<4;a++) for (int b2=0;b2<4;b2++) for (int c=0;c<4;c++) acc[a][b2][c]=0.f;

    const int nk = K/64;
    int cons = 0;
    for (int kt = 0; kt < nk; kt++){
        if (kt+1 < nk) cp_wait1(); else cp_wait0();
        __syncthreads();
        if (kt+2 < nk){
            int st = cons + 2; if (st >= 3) st -= 3;
            loadtile(st, (kt+2)*64);
        }
        uint32_t baseA = sS + cons*32768, baseB = baseA + 16384;
        #pragma unroll
        for (int ks = 0; ks < 4; ks++){
            uint32_t arg[4][4];
            #pragma unroll
            for (int mi = 0; mi < 4; mi++){
                int row = wm + mi*16 + (lane & 15);
                int col = ks*16 + (lane >> 4)*8;
                ldm4(arg[mi][0],arg[mi][1],arg[mi][2],arg[mi][3],
                     baseA + row*128 + (((col>>3) ^ (row&7))*16));
            }
            uint32_t brg[4][2];
            #pragma unroll
            for (int nj = 0; nj < 2; nj++){
                int g = lane >> 3;
                int row = wn + nj*16 + (g>>1)*8 + (lane & 7);
                int col = ks*16 + (g & 1)*8;
                uint32_t r0,r1,r2,r3;
                ldm4(r0,r1,r2,r3, baseB + row*128 + (((col>>3) ^ (row&7))*16));
                brg[nj*2][0]=r0; brg[nj*2][1]=r1; brg[nj*2+1][0]=r2; brg[nj*2+1][1]=r3;
            }
            #pragma unroll
            for (int mi=0;mi<4;mi++)
                #pragma unroll
                for (int nf=0;nf<4;nf++)
                    mma16816(acc[mi][nf], arg[mi][0],arg[mi][1],arg[mi][2],arg[mi][3],
                             brg[nf][0],brg[nf][1]);
        }
        if (++cons == 3) cons = 0;
    }

    __half* dsth = Ch; int coff = 0; int Nd = DIM; bool rope = true; float vs = 1.f;
    if (EPI == 3){
        if (bn < 4096)      { dsth = Ch; coff = 0;    Nd = DIM; rope = true; vs = QSCALE; }
        else if (bn < 5120) { dsth = Kh; coff = 4096; Nd = KVD; rope = true; }
        else                { dsth = Vh; coff = 5120; Nd = KVD; rope = false; }
    }
    #pragma unroll
    for (int mi=0;mi<4;mi++){
        int r0 = bm + wm + mi*16 + (lane>>2), r1 = r0 + 8;
        #pragma unroll
        for (int nf=0;nf<4;nf++){
            int c0 = bn + wn + nf*8 + 2*(lane&3);
            float v0=acc[mi][nf][0], v1=acc[mi][nf][1], v2=acc[mi][nf][2], v3=acc[mi][nf][3];
            if (EPI == 2){
                float2 a01 = make_float2(v0, v1), a23 = make_float2(v2, v3);
                *(float2*)(Cf + (size_t)r0*N + c0) = a01;
                *(float2*)(Cf + (size_t)r1*N + c0) = a23;
            } else {
                int col = c0 - coff;
                if (rope){
                    v0 *= vs; v1 *= vs; v2 *= vs; v3 *= vs;
                    int i0 = (c0 & (HD-1)) >> 1;
                    float cs = cosp[r0*64 + i0], sn = sinp[r0*64 + i0];
                    dsth[(size_t)r0*Nd + col]   = __float2half_rn(v0*cs - v1*sn);
                    dsth[(size_t)r0*Nd + col+1] = __float2half_rn(v0*sn + v1*cs);
                    cs = cosp[r1*64 + i0]; sn = sinp[r1*64 + i0];
                    dsth[(size_t)r1*Nd + col]   = __float2half_rn(v2*cs - v3*sn);
                    dsth[(size_t)r1*Nd + col+1] = __float2half_rn(v2*sn + v3*cs);
                } else {
                    dsth[(size_t)r0*Nd + col]   = __float2half_rn(v0);
                    dsth[(size_t)r0*Nd + col+1] = __float2half_rn(v1);
                    dsth[(size_t)r1*Nd + col]   = __float2half_rn(v2);
                    dsth[(size_t)r1*Nd + col+1] = __float2half_rn(v3);
                }
            }
        }
    }
}

// causal GQA flash attention for qb in [qb_off, qb_off+gridDim.x). Heavy tiles first.
// Q pre-scaled by (1/sqrt(hd))*log2(e): softmax is pure base-2.
__global__ __launch_bounds__(256) void flash_k(const __half* __restrict__ Q, const __half* __restrict__ Kg,
                                               const __half* __restrict__ Vg, __half* __restrict__ O,
                                               int qb_off){
    extern __shared__ __half smemh[];
    __half* Qs = smemh;
    __half* Ks = smemh + 128*128;
    __half* Vs = Ks + 2*64*128;
    const int tid = threadIdx.x, lane = tid & 31, warp = tid >> 5;
    const int qb = qb_off + (gridDim.x - 1 - blockIdx.x);
    const int h = blockIdx.y, kvh = h >> 2;
    uint32_t sQ = cvta_s(Qs), sK = cvta_s(Ks), sV = cvta_s(Vs);

    auto loadKV = [&](int stage, int j){
        const __half* kg = Kg + (size_t)(j*64)*KVD + kvh*HD;
        const __half* vg = Vg + (size_t)(j*64)*KVD + kvh*HD;
        #pragma unroll
        for (int i = 0; i < 4; i++){
            int cid = tid + i*256;
            int row = cid >> 4, ch = cid & 15, sw = ch ^ (row & 7);
            cp16(sK + stage*16384 + row*256 + sw*16, kg + (size_t)row*KVD + ch*8);
            cp16(sV + stage*16384 + row*256 + sw*16, vg + (size_t)row*KVD + ch*8);
        }
        cp_commit();
    };
    const int jmax = 2*qb + 1;
    loadKV(0, 0); loadKV(1, 1);

    {
        const __half* qg = Q + (size_t)(qb*128)*DIM + h*HD;
        #pragma unroll
        for (int i = 0; i < 8; i++){
            int cid = tid + i*256;
            int row = cid >> 4, ch = cid & 15, sw = ch ^ (row & 7);
            *(uint4*)((char*)Qs + row*256 + sw*16) = *(const uint4*)(qg + (size_t)row*DIM + ch*8);
        }
    }

    float o[16][4];
    #pragma unroll
    for (int i=0;i<16;i++){ o[i][0]=0.f;o[i][1]=0.f;o[i][2]=0.f;o[i][3]=0.f; }
    const float NEGINF = __int_as_float(0xff800000);
    float m0 = NEGINF, m1 = NEGINF, l0 = 0.f, l1 = 0.f;
    const int wm = warp*16;
    const int r0g = qb*128 + wm + (lane>>2), r1g = r0g + 8;

    for (int j = 0; j <= jmax; j++){
        if (j < jmax) cp_wait1(); else cp_wait0();
        __syncthreads();
        uint32_t bK = sK + (j&1)*16384, bV = sV + (j&1)*16384;

        float sacc[8][4];
        #pragma unroll
        for (int f=0;f<8;f++){ sacc[f][0]=0.f;sacc[f][1]=0.f;sacc[f][2]=0.f;sacc[f][3]=0.f; }

        #pragma unroll
        for (int ks = 0; ks < 8; ks++){
            int row = wm + (lane & 15);
            int col = ks*16 + (lane >> 4)*8;
            uint32_t a0,a1,a2,a3;
            ldm4(a0,a1,a2,a3, sQ + row*256 + (((col>>3) ^ (row&7))*16));
            #pragma unroll
            for (int nj = 0; nj < 4; nj++){
                int g = lane >> 3;
                int brow = nj*16 + (g>>1)*8 + (lane & 7);
                int bcol = ks*16 + (g & 1)*8;
                uint32_t r0,r1,r2,r3;
                ldm4(r0,r1,r2,r3, bK + brow*256 + (((bcol>>3) ^ (brow&7))*16));
                mma16816(sacc[nj*2],   a0,a1,a2,a3, r0,r1);
                mma16816(sacc[nj*2+1], a0,a1,a2,a3, r2,r3);
            }
        }

        const bool masked = (j >= 2*qb);
        float mx0 = NEGINF, mx1 = NEGINF;
        #pragma unroll
        for (int f = 0; f < 8; f++){
            float v0 = sacc[f][0], v1 = sacc[f][1];
            float v2 = sacc[f][2], v3 = sacc[f][3];
            if (masked){
                int c0 = j*64 + f*8 + 2*(lane & 3);
                if (c0   > r0g) v0 = NEGINF;
                if (c0+1 > r0g) v1 = NEGINF;
                if (c0   > r1g) v2 = NEGINF;
                if (c0+1 > r1g) v3 = NEGINF;
                sacc[f][0]=v0; sacc[f][1]=v1; sacc[f][2]=v2; sacc[f][3]=v3;
            }
            mx0 = fmaxf(mx0, fmaxf(v0, v1));
            mx1 = fmaxf(mx1, fmaxf(v2, v3));
        }
        mx0 = fmaxf(mx0, __shfl_xor_sync(~0u, mx0, 1));
        mx0 = fmaxf(mx0, __shfl_xor_sync(~0u, mx0, 2));
        mx1 = fmaxf(mx1, __shfl_xor_sync(~0u, mx1, 1));
        mx1 = fmaxf(mx1, __shfl_xor_sync(~0u, mx1, 2));
        float nm0 = fmaxf(m0, mx0), nm1 = fmaxf(m1, mx1);
        float al0 = exp2f(m0 - nm0), al1 = exp2f(m1 - nm1);
        m0 = nm0; m1 = nm1;

        float rs0 = 0.f, rs1 = 0.f;
        uint32_t pk[8][2];
        #pragma unroll
        for (int f = 0; f < 8; f++){
            float p0 = exp2f(sacc[f][0]-nm0);
            float p1 = exp2f(sacc[f][1]-nm0);
            float p2 = exp2f(sacc[f][2]-nm1);
            float p3 = exp2f(sacc[f][3]-nm1);
            rs0 += p0 + p1; rs1 += p2 + p3;
            __half2 h01 = __floats2half2_rn(p0, p1);
            __half2 h23 = __floats2half2_rn(p2, p3);
            pk[f][0] = *(uint32_t*)&h01;
            pk[f][1] = *(uint32_t*)&h23;
        }
        rs0 += __shfl_xor_sync(~0u, rs0, 1);
        rs0 += __shfl_xor_sync(~0u, rs0, 2);
        rs1 += __shfl_xor_sync(~0u, rs1, 1);
        rs1 += __shfl_xor_sync(~0u, rs1, 2);
        l0 = l0*al0 + rs0; l1 = l1*al1 + rs1;

        #pragma unroll
        for (int nf=0;nf<16;nf++){
            o[nf][0]*=al0; o[nf][1]*=al0; o[nf][2]*=al1; o[nf][3]*=al1;
        }
        #pragma unroll
        for (int ks = 0; ks < 4; ks++){
            uint32_t a0=pk[2*ks][0], a1=pk[2*ks][1], a2=pk[2*ks+1][0], a3=pk[2*ks+1][1];
            #pragma unroll
            for (int nb = 0; nb < 8; nb++){
                int krow = ks*16 + (lane & 15);
                int ncol = nb*16 + (lane >> 4)*8;
                uint32_t b0,b1,b2,b3;
                ldm4t(b0,b1,b2,b3, bV + krow*256 + (((ncol>>3) ^ (krow&7))*16));
                mma16816(o[2*nb],   a0,a1,a2,a3, b0,b1);
                mma16816(o[2*nb+1], a0,a1,a2,a3, b2,b3);
            }
        }
        __syncthreads();
        if (j+2 <= jmax) loadKV(j&1, j+2);
    }

    float inv0 = 1.f/l0, inv1 = 1.f/l1;
    #pragma unroll
    for (int nf=0;nf<16;nf++){
        int c0 = nf*8 + 2*(lane&3);
        O[(size_t)r0g*DIM + h*HD + c0]   = __float2half_rn(o[nf][0]*inv0);
        O[(size_t)r0g*DIM + h*HD + c0+1] = __float2half_rn(o[nf][1]*inv0);
        O[(size_t)r1g*DIM + h*HD + c0]   = __float2half_rn(o[nf][2]*inv1);
        O[(size_t)r1g*DIM + h*HD + c0+1] = __float2half_rn(o[nf][3]*inv1);
    }
}

extern "C" void kernel_launch(void* const* d_in, const int* in_sizes, int n_in,
                              void* d_out, int out_size) {
    const float* x    = (const float*)d_in[0];
    const float* wq   = (const float*)d_in[1];
    const float* wk   = (const float*)d_in[2];
    const float* wv   = (const float*)d_in[3];
    const float* wo   = (const float*)d_in[4];
    const float* fcos = (const float*)d_in[5];
    const float* fsin = (const float*)d_in[6];

    void *p_wqkv,*p_wo,*p_x,*p_q,*p_kb,*p_vb,*p_at,*p_gm;
    cudaGetSymbolAddress(&p_wqkv, g_wqkv); cudaGetSymbolAddress(&p_wo, g_wo);
    cudaGetSymbolAddress(&p_x,  g_x);  cudaGetSymbolAddress(&p_q,  g_q);
    cudaGetSymbolAddress(&p_kb, g_kb); cudaGetSymbolAddress(&p_vb, g_vb);
    cudaGetSymbolAddress(&p_at, g_at); cudaGetSymbolAddress(&p_gm, g_gmax);
    unsigned* gm = (unsigned*)p_gm;
    __half* hqkv = (__half*)p_wqkv; __half* hwo = (__half*)p_wo;
    __half* hx = (__half*)p_x;  __half* hq = (__half*)p_q;
    __half* hk = (__half*)p_kb; __half* hv = (__half*)p_vb;
    __half* ha = (__half*)p_at;

    cudaFuncSetAttribute(gemm_tn<2>, cudaFuncAttributeMaxDynamicSharedMemorySize, 98304);
    cudaFuncSetAttribute(gemm_tn<3>, cudaFuncAttributeMaxDynamicSharedMemorySize, 98304);
    cudaFuncSetAttribute(flash_k,    cudaFuncAttributeMaxDynamicSharedMemorySize, 98304);

    static cudaStream_t s1 = nullptr, s2 = nullptr, s3 = nullptr;
    static cudaEvent_t e00=nullptr,e1=nullptr,e2=nullptr,e3=nullptr,ef2h=nullptr;
    static cudaEvent_t egq=nullptr,eq2=nullptr;
    static cudaEvent_t eAlo=nullptr,eAhi=nullptr,eBlo=nullptr,eBhi=nullptr;
    static cudaEvent_t eolo=nullptr,eoB=nullptr;
    if (!s1){
        cudaStreamCreateWithFlags(&s1, cudaStreamNonBlocking);
        cudaStreamCreateWithFlags(&s2, cudaStreamNonBlocking);
        cudaStreamCreateWithFlags(&s3, cudaStreamNonBlocking);
        cudaEventCreateWithFlags(&e00, cudaEventDisableTiming);
        cudaEventCreateWithFlags(&e1,  cudaEventDisableTiming);
        cudaEventCreateWithFlags(&e2,  cudaEventDisableTiming);
        cudaEventCreateWithFlags(&e3,  cudaEventDisableTiming);
        cudaEventCreateWithFlags(&ef2h,cudaEventDisableTiming);
        cudaEventCreateWithFlags(&egq, cudaEventDisableTiming);
        cudaEventCreateWithFlags(&eq2, cudaEventDisableTiming);
        cudaEventCreateWithFlags(&eAlo,cudaEventDisableTiming);
        cudaEventCreateWithFlags(&eAhi,cudaEventDisableTiming);
        cudaEventCreateWithFlags(&eBlo,cudaEventDisableTiming);
        cudaEventCreateWithFlags(&eBhi,cudaEventDisableTiming);
        cudaEventCreateWithFlags(&eolo,cudaEventDisableTiming);
        cudaEventCreateWithFlags(&eoB, cudaEventDisableTiming);
    }

    // ---- prologue: zero on default; all side streams join capture via e00 ----
    zero_gmax_k<<<1,256>>>(gm);
    cudaEventRecord(e00, 0);

    cudaStreamWaitEvent(s1, e00, 0);
    group_max_w<<<dim3(1,KVD/8),256,0,s1>>>(wk, gm+64);
    quant_k<<<1024,256,0,s1>>>(wk, gm+64, hqkv + (size_t)4096*DIM, KVD*DIM/4, DIM/4);
    cudaEventRecord(e1, s1);

    cudaStreamWaitEvent(s2, e00, 0);
    f2h_k<<<(S_LEN*DIM/4+255)/256,256,0,s2>>>(x, hx, S_LEN*DIM/4);
    cudaEventRecord(ef2h, s2);
    group_max_w<<<dim3(1,KVD/8),256,0,s2>>>(wv, gm+128);
    quant_k<<<1024,256,0,s2>>>(wv, gm+128, hqkv + (size_t)5120*DIM, KVD*DIM/4, DIM/4);
    cudaEventRecord(e2, s2);

    cudaStreamWaitEvent(s3, e00, 0);
    group_max_w<<<dim3(1,DIM/8),256,0,s3>>>(wo, gm+192);
    quant_k<<<2048,256,0,s3>>>(wo, gm+192, hwo, DIM*DIM/4, DIM/4);
    cudaEventRecord(e3, s3);

    // ---- default: gmax(wq), then wq quant split across default (h1) and s1 (h2) ----
    group_max_w<<<dim3(1,DIM/8),256>>>(wq, gm+0);
    cudaEventRecord(egq, 0);

    cudaStreamWaitEvent(s1, egq, 0);   // s1: after wk work, quant wq rows 2048..4095
    quant_k<<<1024,256,0,s1>>>(wq + (size_t)2048*DIM, gm+0,
                               hqkv + (size_t)2048*DIM, 2048*DIM/4, DIM/4);
    cudaEventRecord(eq2, s1);

    quant_k<<<1024,256>>>(wq, gm+0, hqkv, 2048*DIM/4, DIM/4);   // default: rows 0..2047
    cudaStreamWaitEvent(0, ef2h, 0);
    cudaStreamWaitEvent(0, eq2, 0);
    gemm_tn<3><<<dim3(32,8),256,98304>>>(hx, hqkv, hq, hk, hv, nullptr,
                                         0, 0, NQKV, DIM, fcos, fsin);
    cudaEventRecord(eAlo, 0);
    gemm_tn<3><<<dim3(32,8),256,98304>>>(hx, hqkv, hq, hk, hv, nullptr,
                                         1024, 0, NQKV, DIM, fcos, fsin);
    cudaEventRecord(eAhi, 0);

    // ---- s2: QKV B-chunk (N 4096..6143, wk+wv), lo then hi ----
    cudaStreamWaitEvent(s2, e1, 0);
    gemm_tn<3><<<dim3(16,8),256,98304,s2>>>(hx, hqkv, hq, hk, hv, nullptr,
                                            0, 4096, NQKV, DIM, fcos, fsin);
    cudaEventRecord(eBlo, s2);
    gemm_tn<3><<<dim3(16,8),256,98304,s2>>>(hx, hqkv, hq, hk, hv, nullptr,
                                            1024, 4096, NQKV, DIM, fcos, fsin);
    cudaEventRecord(eBhi, s2);

    // ---- s1: flash-lo (qb 0..7) -> O rows 0..1023 ----
    cudaStreamWaitEvent(s1, eAlo, 0);
    cudaStreamWaitEvent(s1, eBlo, 0);
    flash_k<<<dim3(8,32),256,98304,s1>>>(hq, hk, hv, ha, 0);
    cudaStreamWaitEvent(s1, e3, 0);
    gemm_tn<2><<<dim3(32,8),256,98304,s1>>>(ha, hwo, nullptr, nullptr, nullptr, (float*)d_out,
                                            0, 0, DIM, DIM, nullptr, nullptr);
    cudaEventRecord(eolo, s1);

    // ---- s2: flash_B (qb 12..15) -> O rows 1536..2047 ----
    cudaStreamWaitEvent(s2, eAhi, 0);
    flash_k<<<dim3(4,32),256,98304,s2>>>(hq, hk, hv, ha, 12);
    cudaStreamWaitEvent(s2, e3, 0);
    gemm_tn<2><<<dim3(32,4),256,98304,s2>>>(ha, hwo, nullptr, nullptr, nullptr, (float*)d_out,
                                            1536, 0, DIM, DIM, nullptr, nullptr);
    cudaEventRecord(eoB, s2);

    // ---- default: flash_A (qb 8..11) -> O rows 1024..1535, then join ----
    cudaStreamWaitEvent(0, eBhi, 0);
    flash_k<<<dim3(4,32),256,98304>>>(hq, hk, hv, ha, 8);
    cudaStreamWaitEvent(0, e3, 0);
    gemm_tn<2><<<dim3(32,4),256,98304>>>(ha, hwo, nullptr, nullptr, nullptr, (float*)d_out,
                                         1024, 0, DIM, DIM, nullptr, nullptr);
    cudaStreamWaitEvent(0, eolo, 0);
    cudaStreamWaitEvent(0, eoB, 0);
}

// round 17
// speedup vs baseline: 1.0907x; 1.0195x over previous
#include <cuda_runtime.h>
#include <cuda_fp16.h>
#include <cstdint>

#define S_LEN 2048
#define DIM   4096
#define HD    128
#define KVD   1024
#define NQKV  6144

__device__ __half g_wqkv[NQKV*DIM];   // rows 0..4095 wq, 4096..5119 wk, 5120..6143 wv
__device__ __half g_wo[DIM*DIM];
__device__ __half g_x [S_LEN*DIM];
__device__ __half g_q [S_LEN*DIM];
__device__ __half g_kb[S_LEN*KVD];
__device__ __half g_vb[S_LEN*KVD];
__device__ __half g_at[S_LEN*DIM];
__device__ unsigned g_gmax[4*64];

__device__ __forceinline__ uint32_t cvta_s(const void* p){
    return (uint32_t)__cvta_generic_to_shared(p);
}
__device__ __forceinline__ void cp16(uint32_t s, const void* g){
    asm volatile("cp.async.cg.shared.global [%0], [%1], 16;\n" :: "r"(s), "l"(g));
}
__device__ __forceinline__ void cp_commit(){ asm volatile("cp.async.commit_group;\n"); }
__device__ __forceinline__ void cp_wait1(){ asm volatile("cp.async.wait_group 1;\n"); }
__device__ __forceinline__ void cp_wait0(){ asm volatile("cp.async.wait_group 0;\n"); }
__device__ __forceinline__ void ldm4(uint32_t& a,uint32_t& b,uint32_t& c,uint32_t& d, uint32_t addr){
    asm volatile("ldmatrix.sync.aligned.m8n8.x4.shared.b16 {%0,%1,%2,%3},[%4];\n"
                 : "=r"(a),"=r"(b),"=r"(c),"=r"(d) : "r"(addr));
}
__device__ __forceinline__ void ldm4t(uint32_t& a,uint32_t& b,uint32_t& c,uint32_t& d, uint32_t addr){
    asm volatile("ldmatrix.sync.aligned.m8n8.x4.trans.shared.b16 {%0,%1,%2,%3},[%4];\n"
                 : "=r"(a),"=r"(b),"=r"(c),"=r"(d) : "r"(addr));
}
__device__ __forceinline__ void mma16816(float* c, uint32_t a0,uint32_t a1,uint32_t a2,uint32_t a3,
                                         uint32_t b0,uint32_t b1){
    asm volatile("mma.sync.aligned.m16n8k16.row.col.f32.f16.f16.f32 "
                 "{%0,%1,%2,%3},{%4,%5,%6,%7},{%8,%9},{%0,%1,%2,%3};\n"
                 : "+f"(c[0]),"+f"(c[1]),"+f"(c[2]),"+f"(c[3])
                 : "r"(a0),"r"(a1),"r"(a2),"r"(a3),"r"(b0),"r"(b1));
}

// ---------------- quantization ----------------
__global__ void zero_gmax_k(unsigned* gm){ gm[threadIdx.x] = 0u; }

__global__ __launch_bounds__(256) void group_max_w(const float* __restrict__ W,
                                                   unsigned* __restrict__ gm){
    const float4* base = (const float4*)W + (size_t)blockIdx.y*8*1024 + threadIdx.x;
    unsigned m[4] = {0,0,0,0};
    #pragma unroll
    for (int r = 0; r < 8; r++){
        #pragma unroll
        for (int i = 0; i < 4; i++){
            float4 v = base[(size_t)r*1024 + i*256];
            unsigned b0 = __float_as_uint(v.x) & 0x7fffffffu;
            unsigned b1 = __float_as_uint(v.y) & 0x7fffffffu;
            unsigned b2 = __float_as_uint(v.z) & 0x7fffffffu;
            unsigned b3 = __float_as_uint(v.w) & 0x7fffffffu;
            m[i] = max(m[i], max(max(b0,b1), max(b2,b3)));
        }
    }
    __shared__ unsigned red[64];
    if (threadIdx.x < 64) red[threadIdx.x] = 0u;
    __syncthreads();
    #pragma unroll
    for (int i = 0; i < 4; i++)
        atomicMax(&red[(threadIdx.x + i*256) >> 4], m[i]);
    __syncthreads();
    if (threadIdx.x < 64) atomicMax(&gm[threadIdx.x], red[threadIdx.x]);
}

// sh clamp at 31 maps ab==0 to (0x80>>31)==0, so no zero-select is needed.
__global__ __launch_bounds__(256) void quant_k(const float* __restrict__ W,
                                               const unsigned* __restrict__ gm,
                                               __half* __restrict__ out, int n4, int cols4){
    for (int idx = blockIdx.x*blockDim.x + threadIdx.x; idx < n4; idx += gridDim.x*blockDim.x){
        float4 v = ((const float4*)W)[idx];
        unsigned Egb = gm[(idx % cols4) >> 4] >> 23;
        float scale = __uint_as_float((Egb - 7u) << 23);
        float in[4] = {v.x, v.y, v.z, v.w};
        float q[4];
        #pragma unroll
        for (int j = 0; j < 4; j++){
            uint32_t b = __float_as_uint(in[j]);
            uint32_t ab = b & 0x7fffffffu;
            int sm = (int)(0x80u | ((ab >> 16) & 0x7Fu));
            int sh = min((int)Egb - (int)(ab >> 23), 31);
            float r = (float)(sm >> sh) * scale;
            q[j] = __uint_as_float(__float_as_uint(r) | (b & 0x80000000u));
        }
        ((__half2*)out)[2*idx]   = __floats2half2_rn(q[0], q[1]);
        ((__half2*)out)[2*idx+1] = __floats2half2_rn(q[2], q[3]);
    }
}

__global__ void f2h_k(const float* __restrict__ x, __half* __restrict__ o, int n4){
    int i = blockIdx.x*blockDim.x + threadIdx.x;
    if (i < n4){
        float4 v = ((const float4*)x)[i];
        ((__half2*)o)[2*i]   = __floats2half2_rn(v.x, v.y);
        ((__half2*)o)[2*i+1] = __floats2half2_rn(v.z, v.w);
    }
}

// C[M,N] = A[M,K]*B[N,K]^T. block 128x128x64, 8 warps (2m x 4n). 3-stage cp.async.
// EPI: 2 = fp32 out (O proj); 3 = fused QKV routing (Q rope*QS, K rope->Kh, V plain->Vh)
#define QSCALE 0.12752551f   // (1/sqrt(128)) * log2(e), folded into Q
template<int EPI>
__global__ __launch_bounds__(256,2) void gemm_tn(const __half* __restrict__ A, const __half* __restrict__ B,
                                               __half* __restrict__ Ch, __half* __restrict__ Kh,
                                               __half* __restrict__ Vh, float* __restrict__ Cf,
                                               int m_off, int n_off, int N, int K,
                                               const float* __restrict__ cosp, const float* __restrict__ sinp){
    extern __shared__ __half smem[];
    const int tid = threadIdx.x, lane = tid & 31, warp = tid >> 5;
    const int wm = (warp & 1)*64, wn = (warp >> 1)*32;
    const int bm = m_off + blockIdx.y*128, bn = n_off + blockIdx.x*128;
    uint32_t sS = cvta_s(smem);

    auto loadtile = [&](int stage, int k0){
        uint32_t sA = sS + stage*32768, sB = sA + 16384;
        #pragma unroll
        for (int i = 0; i < 4; i++){
            int cid = tid + i*256;
            int row = cid >> 3, ch = cid & 7, sw = ch ^ (row & 7);
            cp16(sA + row*128 + sw*16, A + (size_t)(bm+row)*K + k0 + ch*8);
            cp16(sB + row*128 + sw*16, B + (size_t)(bn+row)*K + k0 + ch*8);
        }
        cp_commit();
    };
    loadtile(0, 0); loadtile(1, 64);

    float acc[4][4][4];
    #pragma unroll
    for (int a=0;a<4;a++) for (int b2=0;b2<4;b2++) for (int c=0;c<4;c++) acc[a][b2][c]=0.f;

    const int nk = K/64;
    int cons = 0;
    for (int kt = 0; kt < nk; kt++){
        if (kt+1 < nk) cp_wait1(); else cp_wait0();
        __syncthreads();
        if (kt+2 < nk){
            int st = cons + 2; if (st >= 3) st -= 3;
            loadtile(st, (kt+2)*64);
        }
        uint32_t baseA = sS + cons*32768, baseB = baseA + 16384;
        #pragma unroll
        for (int ks = 0; ks < 4; ks++){
            uint32_t arg[4][4];
            #pragma unroll
            for (int mi = 0; mi < 4; mi++){
                int row = wm + mi*16 + (lane & 15);
                int col = ks*16 + (lane >> 4)*8;
                ldm4(arg[mi][0],arg[mi][1],arg[mi][2],arg[mi][3],
                     baseA + row*128 + (((col>>3) ^ (row&7))*16));
            }
            uint32_t brg[4][2];
            #pragma unroll
            for (int nj = 0; nj < 2; nj++){
                int g = lane >> 3;
                int row = wn + nj*16 + (g>>1)*8 + (lane & 7);
                int col = ks*16 + (g & 1)*8;
                uint32_t r0,r1,r2,r3;
                ldm4(r0,r1,r2,r3, baseB + row*128 + (((col>>3) ^ (row&7))*16));
                brg[nj*2][0]=r0; brg[nj*2][1]=r1; brg[nj*2+1][0]=r2; brg[nj*2+1][1]=r3;
            }
            #pragma unroll
            for (int mi=0;mi<4;mi++)
                #pragma unroll
                for (int nf=0;nf<4;nf++)
                    mma16816(acc[mi][nf], arg[mi][0],arg[mi][1],arg[mi][2],arg[mi][3],
                             brg[nf][0],brg[nf][1]);
        }
        if (++cons == 3) cons = 0;
    }

    __half* dsth = Ch; int coff = 0; int Nd = DIM; bool rope = true; float vs = 1.f;
    if (EPI == 3){
        if (bn < 4096)      { dsth = Ch; coff = 0;    Nd = DIM; rope = true; vs = QSCALE; }
        else if (bn < 5120) { dsth = Kh; coff = 4096; Nd = KVD; rope = true; }
        else                { dsth = Vh; coff = 5120; Nd = KVD; rope = false; }
    }
    #pragma unroll
    for (int mi=0;mi<4;mi++){
        int r0 = bm + wm + mi*16 + (lane>>2), r1 = r0 + 8;
        #pragma unroll
        for (int nf=0;nf<4;nf++){
            int c0 = bn + wn + nf*8 + 2*(lane&3);
            float v0=acc[mi][nf][0], v1=acc[mi][nf][1], v2=acc[mi][nf][2], v3=acc[mi][nf][3];
            if (EPI == 2){
                float2 a01 = make_float2(v0, v1), a23 = make_float2(v2, v3);
                *(float2*)(Cf + (size_t)r0*N + c0) = a01;
                *(float2*)(Cf + (size_t)r1*N + c0) = a23;
            } else {
                int col = c0 - coff;      // even -> 4B-aligned half2 stores
                if (rope){
                    v0 *= vs; v1 *= vs; v2 *= vs; v3 *= vs;
                    int i0 = (c0 & (HD-1)) >> 1;
                    float cs = cosp[r0*64 + i0], sn = sinp[r0*64 + i0];
                    *(__half2*)(dsth + (size_t)r0*Nd + col) =
                        __floats2half2_rn(v0*cs - v1*sn, v0*sn + v1*cs);
                    cs = cosp[r1*64 + i0]; sn = sinp[r1*64 + i0];
                    *(__half2*)(dsth + (size_t)r1*Nd + col) =
                        __floats2half2_rn(v2*cs - v3*sn, v2*sn + v3*cs);
                } else {
                    *(__half2*)(dsth + (size_t)r0*Nd + col) = __floats2half2_rn(v0, v1);
                    *(__half2*)(dsth + (size_t)r1*Nd + col) = __floats2half2_rn(v2, v3);
                }
            }
        }
    }
}

// causal GQA flash attention for qb in [qb_off, qb_off+gridDim.x). Heavy tiles first.
// Q pre-scaled by (1/sqrt(hd))*log2(e): softmax is pure base-2.
__global__ __launch_bounds__(256) void flash_k(const __half* __restrict__ Q, const __half* __restrict__ Kg,
                                               const __half* __restrict__ Vg, __half* __restrict__ O,
                                               int qb_off){
    extern __shared__ __half smemh[];
    __half* Qs = smemh;
    __half* Ks = smemh + 128*128;
    __half* Vs = Ks + 2*64*128;
    const int tid = threadIdx.x, lane = tid & 31, warp = tid >> 5;
    const int qb = qb_off + (gridDim.x - 1 - blockIdx.x);
    const int h = blockIdx.y, kvh = h >> 2;
    uint32_t sQ = cvta_s(Qs), sK = cvta_s(Ks), sV = cvta_s(Vs);

    auto loadKV = [&](int stage, int j){
        const __half* kg = Kg + (size_t)(j*64)*KVD + kvh*HD;
        const __half* vg = Vg + (size_t)(j*64)*KVD + kvh*HD;
        #pragma unroll
        for (int i = 0; i < 4; i++){
            int cid = tid + i*256;
            int row = cid >> 4, ch = cid & 15, sw = ch ^ (row & 7);
            cp16(sK + stage*16384 + row*256 + sw*16, kg + (size_t)row*KVD + ch*8);
            cp16(sV + stage*16384 + row*256 + sw*16, vg + (size_t)row*KVD + ch*8);
        }
        cp_commit();
    };
    const int jmax = 2*qb + 1;
    loadKV(0, 0); loadKV(1, 1);

    {
        const __half* qg = Q + (size_t)(qb*128)*DIM + h*HD;
        #pragma unroll
        for (int i = 0; i < 8; i++){
            int cid = tid + i*256;
            int row = cid >> 4, ch = cid & 15, sw = ch ^ (row & 7);
            *(uint4*)((char*)Qs + row*256 + sw*16) = *(const uint4*)(qg + (size_t)row*DIM + ch*8);
        }
    }

    float o[16][4];
    #pragma unroll
    for (int i=0;i<16;i++){ o[i][0]=0.f;o[i][1]=0.f;o[i][2]=0.f;o[i][3]=0.f; }
    const float NEGINF = __int_as_float(0xff800000);
    float m0 = NEGINF, m1 = NEGINF, l0 = 0.f, l1 = 0.f;
    const int wm = warp*16;
    const int r0g = qb*128 + wm + (lane>>2), r1g = r0g + 8;

    for (int j = 0; j <= jmax; j++){
        if (j < jmax) cp_wait1(); else cp_wait0();
        __syncthreads();
        uint32_t bK = sK + (j&1)*16384, bV = sV + (j&1)*16384;

        float sacc[8][4];
        #pragma unroll
        for (int f=0;f<8;f++){ sacc[f][0]=0.f;sacc[f][1]=0.f;sacc[f][2]=0.f;sacc[f][3]=0.f; }

        #pragma unroll
        for (int ks = 0; ks < 8; ks++){
            int row = wm + (lane & 15);
            int col = ks*16 + (lane >> 4)*8;
            uint32_t a0,a1,a2,a3;
            ldm4(a0,a1,a2,a3, sQ + row*256 + (((col>>3) ^ (row&7))*16));
            #pragma unroll
            for (int nj = 0; nj < 4; nj++){
                int g = lane >> 3;
                int brow = nj*16 + (g>>1)*8 + (lane & 7);
                int bcol = ks*16 + (g & 1)*8;
                uint32_t r0,r1,r2,r3;
                ldm4(r0,r1,r2,r3, bK + brow*256 + (((bcol>>3) ^ (brow&7))*16));
                mma16816(sacc[nj*2],   a0,a1,a2,a3, r0,r1);
                mma16816(sacc[nj*2+1], a0,a1,a2,a3, r2,r3);
            }
        }

        const bool masked = (j >= 2*qb);
        float mx0 = NEGINF, mx1 = NEGINF;
        #pragma unroll
        for (int f = 0; f < 8; f++){
            float v0 = sacc[f][0], v1 = sacc[f][1];
            float v2 = sacc[f][2], v3 = sacc[f][3];
            if (masked){
                int c0 = j*64 + f*8 + 2*(lane & 3);
                if (c0   > r0g) v0 = NEGINF;
                if (c0+1 > r0g) v1 = NEGINF;
                if (c0   > r1g) v2 = NEGINF;
                if (c0+1 > r1g) v3 = NEGINF;
                sacc[f][0]=v0; sacc[f][1]=v1; sacc[f][2]=v2; sacc[f][3]=v3;
            }
            mx0 = fmaxf(mx0, fmaxf(v0, v1));
            mx1 = fmaxf(mx1, fmaxf(v2, v3));
        }
        mx0 = fmaxf(mx0, __shfl_xor_sync(~0u, mx0, 1));
        mx0 = fmaxf(mx0, __shfl_xor_sync(~0u, mx0, 2));
        mx1 = fmaxf(mx1, __shfl_xor_sync(~0u, mx1, 1));
        mx1 = fmaxf(mx1, __shfl_xor_sync(~0u, mx1, 2));
        float nm0 = fmaxf(m0, mx0), nm1 = fmaxf(m1, mx1);
        float al0 = exp2f(m0 - nm0), al1 = exp2f(m1 - nm1);
        m0 = nm0; m1 = nm1;

        float rs0 = 0.f, rs1 = 0.f;
        uint32_t pk[8][2];
        #pragma unroll
        for (int f = 0; f < 8; f++){
            float p0 = exp2f(sacc[f][0]-nm0);
            float p1 = exp2f(sacc[f][1]-nm0);
            float p2 = exp2f(sacc[f][2]-nm1);
            float p3 = exp2f(sacc[f][3]-nm1);
            rs0 += p0 + p1; rs1 += p2 + p3;
            __half2 h01 = __floats2half2_rn(p0, p1);
            __half2 h23 = __floats2half2_rn(p2, p3);
            pk[f][0] = *(uint32_t*)&h01;
            pk[f][1] = *(uint32_t*)&h23;
        }
        rs0 += __shfl_xor_sync(~0u, rs0, 1);
        rs0 += __shfl_xor_sync(~0u, rs0, 2);
        rs1 += __shfl_xor_sync(~0u, rs1, 1);
        rs1 += __shfl_xor_sync(~0u, rs1, 2);
        l0 = l0*al0 + rs0; l1 = l1*al1 + rs1;

        if (al0 != 1.f || al1 != 1.f){      // exp2(0)==1 exactly: skip identity rescale
            #pragma unroll
            for (int nf=0;nf<16;nf++){
                o[nf][0]*=al0; o[nf][1]*=al0; o[nf][2]*=al1; o[nf][3]*=al1;
            }
        }
        #pragma unroll
        for (int ks = 0; ks < 4; ks++){
            uint32_t a0=pk[2*ks][0], a1=pk[2*ks][1], a2=pk[2*ks+1][0], a3=pk[2*ks+1][1];
            #pragma unroll
            for (int nb = 0; nb < 8; nb++){
                int krow = ks*16 + (lane & 15);
                int ncol = nb*16 + (lane >> 4)*8;
                uint32_t b0,b1,b2,b3;
                ldm4t(b0,b1,b2,b3, bV + krow*256 + (((ncol>>3) ^ (krow&7))*16));
                mma16816(o[2*nb],   a0,a1,a2,a3, b0,b1);
                mma16816(o[2*nb+1], a0,a1,a2,a3, b2,b3);
            }
        }
        __syncthreads();
        if (j+2 <= jmax) loadKV(j&1, j+2);
    }

    float inv0 = 1.f/l0, inv1 = 1.f/l1;
    #pragma unroll
    for (int nf=0;nf<16;nf++){
        int c0 = nf*8 + 2*(lane&3);
        *(__half2*)(O + (size_t)r0g*DIM + h*HD + c0) = __floats2half2_rn(o[nf][0]*inv0, o[nf][1]*inv0);
        *(__half2*)(O + (size_t)r1g*DIM + h*HD + c0) = __floats2half2_rn(o[nf][2]*inv1, o[nf][3]*inv1);
    }
}

extern "C" void kernel_launch(void* const* d_in, const int* in_sizes, int n_in,
                              void* d_out, int out_size) {
    const float* x    = (const float*)d_in[0];
    const float* wq   = (const float*)d_in[1];
    const float* wk   = (const float*)d_in[2];
    const float* wv   = (const float*)d_in[3];
    const float* wo   = (const float*)d_in[4];
    const float* fcos = (const float*)d_in[5];
    const float* fsin = (const float*)d_in[6];

    void *p_wqkv,*p_wo,*p_x,*p_q,*p_kb,*p_vb,*p_at,*p_gm;
    cudaGetSymbolAddress(&p_wqkv, g_wqkv); cudaGetSymbolAddress(&p_wo, g_wo);
    cudaGetSymbolAddress(&p_x,  g_x);  cudaGetSymbolAddress(&p_q,  g_q);
    cudaGetSymbolAddress(&p_kb, g_kb); cudaGetSymbolAddress(&p_vb, g_vb);
    cudaGetSymbolAddress(&p_at, g_at); cudaGetSymbolAddress(&p_gm, g_gmax);
    unsigned* gm = (unsigned*)p_gm;
    __half* hqkv = (__half*)p_wqkv; __half* hwo = (__half*)p_wo;
    __half* hx = (__half*)p_x;  __half* hq = (__half*)p_q;
    __half* hk = (__half*)p_kb; __half* hv = (__half*)p_vb;
    __half* ha = (__half*)p_at;

    cudaFuncSetAttribute(gemm_tn<2>, cudaFuncAttributeMaxDynamicSharedMemorySize, 98304);
    cudaFuncSetAttribute(gemm_tn<3>, cudaFuncAttributeMaxDynamicSharedMemorySize, 98304);
    cudaFuncSetAttribute(flash_k,    cudaFuncAttributeMaxDynamicSharedMemorySize, 98304);

    static cudaStream_t s1 = nullptr, s2 = nullptr, s3 = nullptr;
    static cudaEvent_t e00=nullptr,e1=nullptr,e2=nullptr,e3=nullptr,ef2h=nullptr;
    static cudaEvent_t egq=nullptr,eq2=nullptr;
    static cudaEvent_t eAlo=nullptr,eAhi=nullptr,eBlo=nullptr,eBhi=nullptr;
    static cudaEvent_t eolo=nullptr,eoB=nullptr;
    if (!s1){
        cudaStreamCreateWithFlags(&s1, cudaStreamNonBlocking);
        cudaStreamCreateWithFlags(&s2, cudaStreamNonBlocking);
        cudaStreamCreateWithFlags(&s3, cudaStreamNonBlocking);
        cudaEventCreateWithFlags(&e00, cudaEventDisableTiming);
        cudaEventCreateWithFlags(&e1,  cudaEventDisableTiming);
        cudaEventCreateWithFlags(&e2,  cudaEventDisableTiming);
        cudaEventCreateWithFlags(&e3,  cudaEventDisableTiming);
        cudaEventCreateWithFlags(&ef2h,cudaEventDisableTiming);
        cudaEventCreateWithFlags(&egq, cudaEventDisableTiming);
        cudaEventCreateWithFlags(&eq2, cudaEventDisableTiming);
        cudaEventCreateWithFlags(&eAlo,cudaEventDisableTiming);
        cudaEventCreateWithFlags(&eAhi,cudaEventDisableTiming);
        cudaEventCreateWithFlags(&eBlo,cudaEventDisableTiming);
        cudaEventCreateWithFlags(&eBhi,cudaEventDisableTiming);
        cudaEventCreateWithFlags(&eolo,cudaEventDisableTiming);
        cudaEventCreateWithFlags(&eoB, cudaEventDisableTiming);
    }

    // ---- prologue: zero on default; all side streams join capture via e00 ----
    zero_gmax_k<<<1,256>>>(gm);
    cudaEventRecord(e00, 0);

    cudaStreamWaitEvent(s1, e00, 0);
    group_max_w<<<dim3(1,KVD/8),256,0,s1>>>(wk, gm+64);
    quant_k<<<1024,256,0,s1>>>(wk, gm+64, hqkv + (size_t)4096*DIM, KVD*DIM/4, DIM/4);
    cudaEventRecord(e1, s1);

    cudaStreamWaitEvent(s2, e00, 0);
    f2h_k<<<(S_LEN*DIM/4+255)/256,256,0,s2>>>(x, hx, S_LEN*DIM/4);
    cudaEventRecord(ef2h, s2);
    group_max_w<<<dim3(1,KVD/8),256,0,s2>>>(wv, gm+128);
    quant_k<<<1024,256,0,s2>>>(wv, gm+128, hqkv + (size_t)5120*DIM, KVD*DIM/4, DIM/4);
    cudaEventRecord(e2, s2);

    cudaStreamWaitEvent(s3, e00, 0);
    group_max_w<<<dim3(1,DIM/8),256,0,s3>>>(wo, gm+192);
    quant_k<<<2048,256,0,s3>>>(wo, gm+192, hwo, DIM*DIM/4, DIM/4);
    cudaEventRecord(e3, s3);

    // ---- default: gmax(wq), wq quant split across default and s1 ----
    group_max_w<<<dim3(1,DIM/8),256>>>(wq, gm+0);
    cudaEventRecord(egq, 0);

    cudaStreamWaitEvent(s1, egq, 0);
    quant_k<<<1024,256,0,s1>>>(wq + (size_t)2048*DIM, gm+0,
                               hqkv + (size_t)2048*DIM, 2048*DIM/4, DIM/4);
    cudaEventRecord(eq2, s1);

    quant_k<<<1024,256>>>(wq, gm+0, hqkv, 2048*DIM/4, DIM/4);
    cudaStreamWaitEvent(0, ef2h, 0);
    cudaStreamWaitEvent(0, eq2, 0);
    gemm_tn<3><<<dim3(32,8),256,98304>>>(hx, hqkv, hq, hk, hv, nullptr,
                                         0, 0, NQKV, DIM, fcos, fsin);
    cudaEventRecord(eAlo, 0);
    gemm_tn<3><<<dim3(32,8),256,98304>>>(hx, hqkv, hq, hk, hv, nullptr,
                                         1024, 0, NQKV, DIM, fcos, fsin);
    cudaEventRecord(eAhi, 0);

    // ---- s2: QKV B-chunk (N 4096..6143, wk+wv), lo then hi ----
    cudaStreamWaitEvent(s2, e1, 0);
    gemm_tn<3><<<dim3(16,8),256,98304,s2>>>(hx, hqkv, hq, hk, hv, nullptr,
                                            0, 4096, NQKV, DIM, fcos, fsin);
    cudaEventRecord(eBlo, s2);
    gemm_tn<3><<<dim3(16,8),256,98304,s2>>>(hx, hqkv, hq, hk, hv, nullptr,
                                            1024, 4096, NQKV, DIM, fcos, fsin);
    cudaEventRecord(eBhi, s2);

    // ---- s1: flash-lo (qb 0..7) -> O rows 0..1023 ----
    cudaStreamWaitEvent(s1, eAlo, 0);
    cudaStreamWaitEvent(s1, eBlo, 0);
    flash_k<<<dim3(8,32),256,98304,s1>>>(hq, hk, hv, ha, 0);
    cudaStreamWaitEvent(s1, e3, 0);
    gemm_tn<2><<<dim3(32,8),256,98304,s1>>>(ha, hwo, nullptr, nullptr, nullptr, (float*)d_out,
                                            0, 0, DIM, DIM, nullptr, nullptr);
    cudaEventRecord(eolo, s1);

    // ---- s2: flash_B (qb 12..15) -> O rows 1536..2047 ----
    cudaStreamWaitEvent(s2, eAhi, 0);
    flash_k<<<dim3(4,32),256,98304,s2>>>(hq, hk, hv, ha, 12);
    cudaStreamWaitEvent(s2, e3, 0);
    gemm_tn<2><<<dim3(32,4),256,98304,s2>>>(ha, hwo, nullptr, nullptr, nullptr, (float*)d_out,
                                            1536, 0, DIM, DIM, nullptr, nullptr);
    cudaEventRecord(eoB, s2);

    // ---- default: flash_A (qb 8..11) -> O rows 1024..1535, then join ----
    cudaStreamWaitEvent(0, eBhi, 0);
    flash_k<<<dim3(4,32),256,98304>>>(hq, hk, hv, ha, 8);
    cudaStreamWaitEvent(0, e3, 0);
    gemm_tn<2><<<dim3(32,4),256,98304>>>(ha, hwo, nullptr, nullptr, nullptr, (float*)d_out,
                                         1024, 0, DIM, DIM, nullptr, nullptr);
    cudaStreamWaitEvent(0, eolo, 0);
    cudaStreamWaitEvent(0, eoB, 0);
}